// round 1
// baseline (speedup 1.0000x reference)
#include <cuda_runtime.h>
#include <math.h>

// Problem constants
#define N_TOK 4096
#define IN_D  1024
#define OUT_D 1024
#define E_N   8
#define R_N   16
#define HG_N  256
#define ER_N  (E_N * R_N)   // 128

// Scratch (device globals: no allocation allowed)
__device__ float g_H[N_TOK * HG_N];   // hidden activations (4 MB)
__device__ float g_C[N_TOK * ER_N];   // T then Call, in place (2 MB)

// GEMM tiling
#define BM 128
#define BN 64
#define BK 16
#define NTHR 128

// ---------------------------------------------------------------------------
// K1: [4096 x 384] = X @ [Wg1 | Vflat^T]
//   cols 0..255  : H = relu(X@Wg1 + bg1)  -> g_H
//   cols 256..383: T = X@Vflat^T          -> g_C
// ---------------------------------------------------------------------------
__global__ __launch_bounds__(NTHR) void k_proj(
    const float* __restrict__ X, const float* __restrict__ Wg1,
    const float* __restrict__ V, const float* __restrict__ bg1)
{
    __shared__ float As[2][BK][BM + 4];
    __shared__ float Bs[2][BK][BN + 4];

    const int tid  = threadIdx.x;
    const int tx   = tid & 7;      // 8 col groups
    const int ty   = tid >> 3;     // 16 row groups
    const int row0 = blockIdx.y * BM;
    const int bx   = blockIdx.x;
    const int col0 = bx * BN;              // 0..383
    const bool natural = (bx < 4);         // Wg1 region (j-contiguous)

    float acc[8][8];
#pragma unroll
    for (int i = 0; i < 8; i++)
#pragma unroll
        for (int j = 0; j < 8; j++) acc[i][j] = 0.f;

    float4 ra[4], rb[2];

    auto loadRegs = [&](int kt) {
        const int k0 = kt * BK;
#pragma unroll
        for (int q = 0; q < 4; q++) {
            int u = tid + q * NTHR, r = u >> 2, kc = (u & 3) << 2;
            ra[q] = *reinterpret_cast<const float4*>(X + (size_t)(row0 + r) * IN_D + k0 + kc);
        }
        if (natural) {
#pragma unroll
            for (int q = 0; q < 2; q++) {
                int u = tid + q * NTHR, k = u >> 4, j4 = (u & 15) << 2;
                rb[q] = *reinterpret_cast<const float4*>(Wg1 + (size_t)(k0 + k) * HG_N + col0 + j4);
            }
        } else {
#pragma unroll
            for (int q = 0; q < 2; q++) {
                int u = tid + q * NTHR, j = u >> 2, kc = (u & 3) << 2;
                rb[q] = *reinterpret_cast<const float4*>(V + (size_t)(col0 - 256 + j) * IN_D + k0 + kc);
            }
        }
    };

    auto storeSmem = [&](int p) {
#pragma unroll
        for (int q = 0; q < 4; q++) {
            int u = tid + q * NTHR, r = u >> 2, kc = (u & 3) << 2;
            As[p][kc + 0][r] = ra[q].x; As[p][kc + 1][r] = ra[q].y;
            As[p][kc + 2][r] = ra[q].z; As[p][kc + 3][r] = ra[q].w;
        }
        if (natural) {
#pragma unroll
            for (int q = 0; q < 2; q++) {
                int u = tid + q * NTHR, k = u >> 4, j4 = (u & 15) << 2;
                *reinterpret_cast<float4*>(&Bs[p][k][j4]) = rb[q];
            }
        } else {
#pragma unroll
            for (int q = 0; q < 2; q++) {
                int u = tid + q * NTHR, j = u >> 2, kc = (u & 3) << 2;
                Bs[p][kc + 0][j] = rb[q].x; Bs[p][kc + 1][j] = rb[q].y;
                Bs[p][kc + 2][j] = rb[q].z; Bs[p][kc + 3][j] = rb[q].w;
            }
        }
    };

    const int NT = IN_D / BK;   // 64
    loadRegs(0);
    int p = 0;
    for (int kt = 0; kt < NT; ++kt) {
        storeSmem(p);
        __syncthreads();
        if (kt + 1 < NT) loadRegs(kt + 1);
#pragma unroll
        for (int k = 0; k < BK; k++) {
            float a[8], b[8];
            *reinterpret_cast<float4*>(a)     = *reinterpret_cast<const float4*>(&As[p][k][ty * 8]);
            *reinterpret_cast<float4*>(a + 4) = *reinterpret_cast<const float4*>(&As[p][k][ty * 8 + 4]);
            *reinterpret_cast<float4*>(b)     = *reinterpret_cast<const float4*>(&Bs[p][k][tx * 8]);
            *reinterpret_cast<float4*>(b + 4) = *reinterpret_cast<const float4*>(&Bs[p][k][tx * 8 + 4]);
#pragma unroll
            for (int i = 0; i < 8; i++)
#pragma unroll
                for (int j = 0; j < 8; j++)
                    acc[i][j] = fmaf(a[i], b[j], acc[i][j]);
        }
        p ^= 1;
    }

    if (natural) {
#pragma unroll
        for (int i = 0; i < 8; i++) {
            int row = row0 + ty * 8 + i;
#pragma unroll
            for (int jj = 0; jj < 8; jj += 4) {
                int col = col0 + tx * 8 + jj;
                float4 v;
                v.x = fmaxf(acc[i][jj + 0] + bg1[col + 0], 0.f);
                v.y = fmaxf(acc[i][jj + 1] + bg1[col + 1], 0.f);
                v.z = fmaxf(acc[i][jj + 2] + bg1[col + 2], 0.f);
                v.w = fmaxf(acc[i][jj + 3] + bg1[col + 3], 0.f);
                *reinterpret_cast<float4*>(&g_H[(size_t)row * HG_N + col]) = v;
            }
        }
    } else {
#pragma unroll
        for (int i = 0; i < 8; i++) {
            int row = row0 + ty * 8 + i;
#pragma unroll
            for (int jj = 0; jj < 8; jj += 4) {
                int col = col0 - 256 + tx * 8 + jj;
                float4 v;
                v.x = acc[i][jj + 0]; v.y = acc[i][jj + 1];
                v.z = acc[i][jj + 2]; v.w = acc[i][jj + 3];
                *reinterpret_cast<float4*>(&g_C[(size_t)row * ER_N + col]) = v;
            }
        }
    }
}

// ---------------------------------------------------------------------------
// K2: per-token gating. logits = H@Wg2 + bg2; top-2; softmax;
//     rewrite g_C row in place: Call[j] = gate_k * S[e,r] * T[j] for selected
//     experts, 0 otherwise. One warp per token.
// ---------------------------------------------------------------------------
__global__ __launch_bounds__(256) void k_gate(
    const float* __restrict__ Wg2, const float* __restrict__ bg2,
    const float* __restrict__ S)
{
    const int warp = threadIdx.x >> 5;
    const int lane = threadIdx.x & 31;
    const int n = blockIdx.x * 8 + warp;
    if (n >= N_TOK) return;

    float acc[E_N];
#pragma unroll
    for (int e = 0; e < E_N; e++) acc[e] = 0.f;

    const float* h = g_H + (size_t)n * HG_N;
    for (int hh = lane; hh < HG_N; hh += 32) {
        float hv = h[hh];
        const float* w = Wg2 + (size_t)hh * E_N;
#pragma unroll
        for (int e = 0; e < E_N; e++) acc[e] = fmaf(hv, w[e], acc[e]);
    }
#pragma unroll
    for (int e = 0; e < E_N; e++) {
#pragma unroll
        for (int off = 16; off; off >>= 1)
            acc[e] += __shfl_xor_sync(0xffffffffu, acc[e], off);
        acc[e] += bg2[e];
    }

    // top-2 (strict > : first index wins ties, matching jax top_k)
    int i0 = 0; float v0 = acc[0];
#pragma unroll
    for (int e = 1; e < E_N; e++) if (acc[e] > v0) { v0 = acc[e]; i0 = e; }
    int i1 = -1; float v1 = -3.0e38f;
#pragma unroll
    for (int e = 0; e < E_N; e++) if (e != i0 && acc[e] > v1) { v1 = acc[e]; i1 = e; }

    float e1 = expf(v1 - v0);
    float s  = 1.f + e1;
    float g0 = 1.f / s;
    float g1 = e1 / s;

    float* c = g_C + (size_t)n * ER_N;
#pragma unroll
    for (int q = 0; q < 4; q++) {
        int j = lane + q * 32;
        float t = c[j];
        int e = j >> 4, r = j & 15;
        float g = (e == i0) ? g0 : ((e == i1) ? g1 : 0.f);
        c[j] = g * S[e * R_N + r] * t;
    }
}

// ---------------------------------------------------------------------------
// K3: out[4096,1024] = X@Wm^T + Call@Uf + bias
//     Single GEMM, K = 1024 + 128 = 1152. k-tiles >= 64 source Call / U_all.
//     U_all [E,OUT,R] is already k-contiguous (r fastest) for transposed load.
// ---------------------------------------------------------------------------
__global__ __launch_bounds__(NTHR) void k_main(
    const float* __restrict__ X, const float* __restrict__ Wm,
    const float* __restrict__ U, const float* __restrict__ bias,
    float* __restrict__ out)
{
    __shared__ float As[2][BK][BM + 4];
    __shared__ float Bs[2][BK][BN + 4];

    const int tid  = threadIdx.x;
    const int tx   = tid & 7;
    const int ty   = tid >> 3;
    const int row0 = blockIdx.y * BM;
    const int col0 = blockIdx.x * BN;

    float acc[8][8];
#pragma unroll
    for (int i = 0; i < 8; i++)
#pragma unroll
        for (int j = 0; j < 8; j++) acc[i][j] = 0.f;

    float4 ra[4], rb[2];

    auto loadRegs = [&](int kt) {
        const int k0 = kt * BK;
        if (k0 < IN_D) {
#pragma unroll
            for (int q = 0; q < 4; q++) {
                int u = tid + q * NTHR, r = u >> 2, kc = (u & 3) << 2;
                ra[q] = *reinterpret_cast<const float4*>(X + (size_t)(row0 + r) * IN_D + k0 + kc);
            }
#pragma unroll
            for (int q = 0; q < 2; q++) {
                int u = tid + q * NTHR, j = u >> 2, kc = (u & 3) << 2;
                rb[q] = *reinterpret_cast<const float4*>(Wm + (size_t)(col0 + j) * IN_D + k0 + kc);
            }
        } else {
            const int kk = k0 - IN_D;        // 0..127, multiple of 16
            const int e  = kk >> 4;          // expert index
#pragma unroll
            for (int q = 0; q < 4; q++) {
                int u = tid + q * NTHR, r = u >> 2, kc = (u & 3) << 2;
                ra[q] = *reinterpret_cast<const float4*>(&g_C[(size_t)(row0 + r) * ER_N + kk + kc]);
            }
#pragma unroll
            for (int q = 0; q < 2; q++) {
                int u = tid + q * NTHR, j = u >> 2, kc = (u & 3) << 2;
                rb[q] = *reinterpret_cast<const float4*>(U + (size_t)e * OUT_D * R_N + (size_t)(col0 + j) * R_N + kc);
            }
        }
    };

    auto storeSmem = [&](int p) {
#pragma unroll
        for (int q = 0; q < 4; q++) {
            int u = tid + q * NTHR, r = u >> 2, kc = (u & 3) << 2;
            As[p][kc + 0][r] = ra[q].x; As[p][kc + 1][r] = ra[q].y;
            As[p][kc + 2][r] = ra[q].z; As[p][kc + 3][r] = ra[q].w;
        }
#pragma unroll
        for (int q = 0; q < 2; q++) {
            int u = tid + q * NTHR, j = u >> 2, kc = (u & 3) << 2;
            Bs[p][kc + 0][j] = rb[q].x; Bs[p][kc + 1][j] = rb[q].y;
            Bs[p][kc + 2][j] = rb[q].z; Bs[p][kc + 3][j] = rb[q].w;
        }
    };

    const int NT = (IN_D + ER_N) / BK;   // 72
    loadRegs(0);
    int p = 0;
    for (int kt = 0; kt < NT; ++kt) {
        storeSmem(p);
        __syncthreads();
        if (kt + 1 < NT) loadRegs(kt + 1);
#pragma unroll
        for (int k = 0; k < BK; k++) {
            float a[8], b[8];
            *reinterpret_cast<float4*>(a)     = *reinterpret_cast<const float4*>(&As[p][k][ty * 8]);
            *reinterpret_cast<float4*>(a + 4) = *reinterpret_cast<const float4*>(&As[p][k][ty * 8 + 4]);
            *reinterpret_cast<float4*>(b)     = *reinterpret_cast<const float4*>(&Bs[p][k][tx * 8]);
            *reinterpret_cast<float4*>(b + 4) = *reinterpret_cast<const float4*>(&Bs[p][k][tx * 8 + 4]);
#pragma unroll
            for (int i = 0; i < 8; i++)
#pragma unroll
                for (int j = 0; j < 8; j++)
                    acc[i][j] = fmaf(a[i], b[j], acc[i][j]);
        }
        p ^= 1;
    }

#pragma unroll
    for (int i = 0; i < 8; i++) {
        int row = row0 + ty * 8 + i;
#pragma unroll
        for (int jj = 0; jj < 8; jj += 4) {
            int col = col0 + tx * 8 + jj;
            float4 v;
            v.x = acc[i][jj + 0] + bias[col + 0];
            v.y = acc[i][jj + 1] + bias[col + 1];
            v.z = acc[i][jj + 2] + bias[col + 2];
            v.w = acc[i][jj + 3] + bias[col + 3];
            *reinterpret_cast<float4*>(&out[(size_t)row * OUT_D + col]) = v;
        }
    }
}

// ---------------------------------------------------------------------------
extern "C" void kernel_launch(void* const* d_in, const int* in_sizes, int n_in,
                              void* d_out, int out_size)
{
    const float* x    = (const float*)d_in[0];
    const float* wm   = (const float*)d_in[1];
    const float* bias = (const float*)d_in[2];
    const float* U    = (const float*)d_in[3];
    const float* S    = (const float*)d_in[4];
    const float* V    = (const float*)d_in[5];
    const float* Wg1  = (const float*)d_in[6];
    const float* bg1  = (const float*)d_in[7];
    const float* Wg2  = (const float*)d_in[8];
    const float* bg2  = (const float*)d_in[9];
    float* out = (float*)d_out;

    dim3 g1((HG_N + ER_N) / BN, N_TOK / BM);   // (6, 32)
    k_proj<<<g1, NTHR>>>(x, Wg1, V, bg1);

    k_gate<<<N_TOK / 8, 256>>>(Wg2, bg2, S);

    dim3 g3(OUT_D / BN, N_TOK / BM);           // (16, 32)
    k_main<<<g3, NTHR>>>(x, wm, U, bias, out);
}

// round 4
// speedup vs baseline: 3.4896x; 3.4896x over previous
#include <cuda_runtime.h>
#include <cstdint>
#include <math.h>

// ---------------------------------------------------------------- constants
#define N_TOK 4096
#define IN_D  1024
#define OUT_D 1024
#define E_N   8
#define R_N   16
#define HG_N  256
#define ER_N  128

// scratch (no allocation allowed)
__device__ float g_H[(size_t)N_TOK * HG_N];     // 4 MB
__device__ float g_C[(size_t)N_TOK * ER_N];     // 2 MB
__device__ float g_Wg1T[(size_t)HG_N * IN_D];   // 1 MB, transposed gate W1

// ---------------------------------------------------------------- helpers
// round-to-nearest tf32: cvt.rna.tf32.f32 requires .b32 destination
__device__ __forceinline__ uint32_t tf32r(float x) {
    uint32_t r; asm("cvt.rna.tf32.f32 %0, %1;" : "=r"(r) : "f"(x)); return r;
}

__device__ __forceinline__ void mma_tf32(float& d0, float& d1, float& d2, float& d3,
                                         uint32_t a0, uint32_t a1, uint32_t a2, uint32_t a3,
                                         uint32_t b0, uint32_t b1) {
    asm volatile(
        "mma.sync.aligned.m16n8k8.row.col.f32.tf32.tf32.f32 "
        "{%0,%1,%2,%3}, {%4,%5,%6,%7}, {%8,%9}, {%0,%1,%2,%3};"
        : "+f"(d0), "+f"(d1), "+f"(d2), "+f"(d3)
        : "r"(a0), "r"(a1), "r"(a2), "r"(a3), "r"(b0), "r"(b1));
}

// ---------------------------------------------------------------- tiling
#define BM   128
#define BN   128
#define BK   32
#define BKP  36                       // padded k extent (conflict-free)
#define NTHR 256
#define ASTRIDE (BM * BKP)            // floats per A stage
#define BSTRIDE (BN * BKP)
#define SMEM_FLOATS (2 * ASTRIDE + 2 * BSTRIDE)
#define SMEM_BYTES  (SMEM_FLOATS * 4)   // 73728

// smem layout: As[2][BM][BKP] then Bs[2][BN][BKP]
#define AS(s, p, m, k) (s)[((p) * BM + (m)) * BKP + (k)]
#define BS(s, p, n, k) (s)[2 * ASTRIDE + ((p) * BN + (n)) * BKP + (k)]

// ---------------------------------------------------------------- transpose Wg1
__global__ void k_tr(const float* __restrict__ Wg1) {
    __shared__ float t[32][33];
    int bx = blockIdx.x * 32;   // hg
    int by = blockIdx.y * 32;   // in
    int x = threadIdx.x, y = threadIdx.y;
    t[y][x] = Wg1[(size_t)(by + y) * HG_N + bx + x];
    __syncthreads();
    g_Wg1T[(size_t)(bx + y) * IN_D + by + x] = t[x][y];
}

// ---------------------------------------------------------------- K1: proj
// bx 0,1 -> H = relu(X@Wg1 + bg1) (via g_Wg1T);  bx 2 -> T = X@V^T -> g_C
__global__ void __launch_bounds__(NTHR, 1) k_proj_mma(
    const float* __restrict__ X, const float* __restrict__ V,
    const float* __restrict__ bg1)
{
    extern __shared__ float smem[];
    const int tid = threadIdx.x, wid = tid >> 5, lane = tid & 31;
    const int ly = lane >> 2, lx = lane & 3;
    const int bx = blockIdx.x;
    const int row0 = blockIdx.y * BM;
    const int wm = (wid & 1) * 64;    // warp m offset
    const int wn = (wid >> 1) * 32;   // warp n offset
    const float* Bsrc = (bx < 2) ? (g_Wg1T + (size_t)bx * BN * IN_D) : V;

    float acc[4][4][4];
#pragma unroll
    for (int mt = 0; mt < 4; mt++)
#pragma unroll
        for (int nt = 0; nt < 4; nt++)
#pragma unroll
            for (int r = 0; r < 4; r++) acc[mt][nt][r] = 0.f;

    float4 ra[4], rb[4];
    auto loadRegs = [&](int k0) {
#pragma unroll
        for (int q = 0; q < 4; q++) {
            int u = tid + q * NTHR, m = u >> 3, kc = (u & 7) << 2;
            ra[q] = *(const float4*)(X + (size_t)(row0 + m) * IN_D + k0 + kc);
        }
#pragma unroll
        for (int q = 0; q < 4; q++) {
            int u = tid + q * NTHR, n = u >> 3, kc = (u & 7) << 2;
            rb[q] = *(const float4*)(Bsrc + (size_t)n * IN_D + k0 + kc);
        }
    };
    auto storeSmem = [&](int p) {
#pragma unroll
        for (int q = 0; q < 4; q++) {
            int u = tid + q * NTHR, m = u >> 3, kc = (u & 7) << 2;
            float* d = &AS(smem, p, m, kc);
            d[0] = __uint_as_float(tf32r(ra[q].x));
            d[1] = __uint_as_float(tf32r(ra[q].y));
            d[2] = __uint_as_float(tf32r(ra[q].z));
            d[3] = __uint_as_float(tf32r(ra[q].w));
        }
#pragma unroll
        for (int q = 0; q < 4; q++) {
            int u = tid + q * NTHR, n = u >> 3, kc = (u & 7) << 2;
            float* d = &BS(smem, p, n, kc);
            d[0] = __uint_as_float(tf32r(rb[q].x));
            d[1] = __uint_as_float(tf32r(rb[q].y));
            d[2] = __uint_as_float(tf32r(rb[q].z));
            d[3] = __uint_as_float(tf32r(rb[q].w));
        }
    };

    const int NT = IN_D / BK;   // 32
    loadRegs(0);
    for (int i = 0; i < NT; i++) {
        int p = i & 1;
        storeSmem(p);
        __syncthreads();
        if (i + 1 < NT) loadRegs((i + 1) * BK);
#pragma unroll
        for (int ks = 0; ks < 4; ks++) {
            const int k0 = ks * 8;
            uint32_t af[4][4], bf[4][2];
#pragma unroll
            for (int mt = 0; mt < 4; mt++) {
                const float* a = &AS(smem, p, wm + mt * 16 + ly, k0 + lx);
                af[mt][0] = __float_as_uint(a[0]);
                af[mt][1] = __float_as_uint(a[8 * BKP]);
                af[mt][2] = __float_as_uint(a[4]);
                af[mt][3] = __float_as_uint(a[8 * BKP + 4]);
            }
#pragma unroll
            for (int nt = 0; nt < 4; nt++) {
                const float* b = &BS(smem, p, wn + nt * 8 + ly, k0 + lx);
                bf[nt][0] = __float_as_uint(b[0]);
                bf[nt][1] = __float_as_uint(b[4]);
            }
#pragma unroll
            for (int mt = 0; mt < 4; mt++)
#pragma unroll
                for (int nt = 0; nt < 4; nt++)
                    mma_tf32(acc[mt][nt][0], acc[mt][nt][1], acc[mt][nt][2], acc[mt][nt][3],
                             af[mt][0], af[mt][1], af[mt][2], af[mt][3],
                             bf[nt][0], bf[nt][1]);
        }
        __syncthreads();
    }

    // epilogue
#pragma unroll
    for (int mt = 0; mt < 4; mt++) {
        int row = row0 + wm + mt * 16 + ly;
#pragma unroll
        for (int nt = 0; nt < 4; nt++) {
            int col = wn + nt * 8 + 2 * lx;     // within [0, BN)
            if (bx < 2) {
                int colh = bx * BN + col;
                float b0 = bg1[colh], b1 = bg1[colh + 1];
                float2 v0, v1;
                v0.x = fmaxf(acc[mt][nt][0] + b0, 0.f);
                v0.y = fmaxf(acc[mt][nt][1] + b1, 0.f);
                v1.x = fmaxf(acc[mt][nt][2] + b0, 0.f);
                v1.y = fmaxf(acc[mt][nt][3] + b1, 0.f);
                *(float2*)(g_H + (size_t)row * HG_N + colh) = v0;
                *(float2*)(g_H + (size_t)(row + 8) * HG_N + colh) = v1;
            } else {
                float2 v0 = {acc[mt][nt][0], acc[mt][nt][1]};
                float2 v1 = {acc[mt][nt][2], acc[mt][nt][3]};
                *(float2*)(g_C + (size_t)row * ER_N + col) = v0;
                *(float2*)(g_C + (size_t)(row + 8) * ER_N + col) = v1;
            }
        }
    }
}

// ---------------------------------------------------------------- K2: gate
__global__ void __launch_bounds__(256) k_gate(
    const float* __restrict__ Wg2, const float* __restrict__ bg2,
    const float* __restrict__ S)
{
    const int warp = threadIdx.x >> 5;
    const int lane = threadIdx.x & 31;
    const int n = blockIdx.x * 8 + warp;
    if (n >= N_TOK) return;

    float acc[E_N];
#pragma unroll
    for (int e = 0; e < E_N; e++) acc[e] = 0.f;

    const float* h = g_H + (size_t)n * HG_N;
    for (int hh = lane; hh < HG_N; hh += 32) {
        float hv = h[hh];
        const float* w = Wg2 + (size_t)hh * E_N;
#pragma unroll
        for (int e = 0; e < E_N; e++) acc[e] = fmaf(hv, w[e], acc[e]);
    }
#pragma unroll
    for (int e = 0; e < E_N; e++) {
#pragma unroll
        for (int off = 16; off; off >>= 1)
            acc[e] += __shfl_xor_sync(0xffffffffu, acc[e], off);
        acc[e] += bg2[e];
    }

    int i0 = 0; float v0 = acc[0];
#pragma unroll
    for (int e = 1; e < E_N; e++) if (acc[e] > v0) { v0 = acc[e]; i0 = e; }
    int i1 = -1; float v1 = -3.0e38f;
#pragma unroll
    for (int e = 0; e < E_N; e++) if (e != i0 && acc[e] > v1) { v1 = acc[e]; i1 = e; }

    float e1 = expf(v1 - v0);
    float s  = 1.f + e1;
    float g0 = 1.f / s;
    float g1 = e1 / s;

    float* c = g_C + (size_t)n * ER_N;
#pragma unroll
    for (int q = 0; q < 4; q++) {
        int j = lane + q * 32;
        float t = c[j];
        int e = j >> 4, r = j & 15;
        float g = (e == i0) ? g0 : ((e == i1) ? g1 : 0.f);
        c[j] = g * S[e * R_N + r] * t;
    }
}

// ---------------------------------------------------------------- K3: main
// out = X@Wm^T + Call@Uf + bias   (K = 1024 + 128 = 1152)
__global__ void __launch_bounds__(NTHR, 1) k_main_mma(
    const float* __restrict__ X, const float* __restrict__ Wm,
    const float* __restrict__ U, const float* __restrict__ bias,
    float* __restrict__ out)
{
    extern __shared__ float smem[];
    const int tid = threadIdx.x, wid = tid >> 5, lane = tid & 31;
    const int ly = lane >> 2, lx = lane & 3;
    const int row0 = blockIdx.y * BM;
    const int col0 = blockIdx.x * BN;
    const int wm = (wid & 1) * 64;
    const int wn = (wid >> 1) * 32;

    float acc[4][4][4];
#pragma unroll
    for (int mt = 0; mt < 4; mt++)
#pragma unroll
        for (int nt = 0; nt < 4; nt++)
#pragma unroll
            for (int r = 0; r < 4; r++) acc[mt][nt][r] = 0.f;

    float4 ra[4], rb[4];
    auto loadRegs = [&](int k0) {
        if (k0 < IN_D) {
#pragma unroll
            for (int q = 0; q < 4; q++) {
                int u = tid + q * NTHR, m = u >> 3, kc = (u & 7) << 2;
                ra[q] = *(const float4*)(X + (size_t)(row0 + m) * IN_D + k0 + kc);
            }
#pragma unroll
            for (int q = 0; q < 4; q++) {
                int u = tid + q * NTHR, n = u >> 3, kc = (u & 7) << 2;
                rb[q] = *(const float4*)(Wm + (size_t)(col0 + n) * IN_D + k0 + kc);
            }
        } else {
            const int kk = k0 - IN_D;    // multiple of 32
#pragma unroll
            for (int q = 0; q < 4; q++) {
                int u = tid + q * NTHR, m = u >> 3, kc = (u & 7) << 2;
                ra[q] = *(const float4*)(g_C + (size_t)(row0 + m) * ER_N + kk + kc);
            }
#pragma unroll
            for (int q = 0; q < 4; q++) {
                int u = tid + q * NTHR, n = u >> 3, kc = (u & 7) << 2;
                int kg = kk + kc, e = kg >> 4, r0 = kg & 15;
                rb[q] = *(const float4*)(U + ((size_t)e * OUT_D + (col0 + n)) * R_N + r0);
            }
        }
    };
    auto storeSmem = [&](int p) {
#pragma unroll
        for (int q = 0; q < 4; q++) {
            int u = tid + q * NTHR, m = u >> 3, kc = (u & 7) << 2;
            float* d = &AS(smem, p, m, kc);
            d[0] = __uint_as_float(tf32r(ra[q].x));
            d[1] = __uint_as_float(tf32r(ra[q].y));
            d[2] = __uint_as_float(tf32r(ra[q].z));
            d[3] = __uint_as_float(tf32r(ra[q].w));
        }
#pragma unroll
        for (int q = 0; q < 4; q++) {
            int u = tid + q * NTHR, n = u >> 3, kc = (u & 7) << 2;
            float* d = &BS(smem, p, n, kc);
            d[0] = __uint_as_float(tf32r(rb[q].x));
            d[1] = __uint_as_float(tf32r(rb[q].y));
            d[2] = __uint_as_float(tf32r(rb[q].z));
            d[3] = __uint_as_float(tf32r(rb[q].w));
        }
    };

    const int NT = (IN_D + ER_N) / BK;   // 36
    loadRegs(0);
    for (int i = 0; i < NT; i++) {
        int p = i & 1;
        storeSmem(p);
        __syncthreads();
        if (i + 1 < NT) loadRegs((i + 1) * BK);
#pragma unroll
        for (int ks = 0; ks < 4; ks++) {
            const int k0 = ks * 8;
            uint32_t af[4][4], bf[4][2];
#pragma unroll
            for (int mt = 0; mt < 4; mt++) {
                const float* a = &AS(smem, p, wm + mt * 16 + ly, k0 + lx);
                af[mt][0] = __float_as_uint(a[0]);
                af[mt][1] = __float_as_uint(a[8 * BKP]);
                af[mt][2] = __float_as_uint(a[4]);
                af[mt][3] = __float_as_uint(a[8 * BKP + 4]);
            }
#pragma unroll
            for (int nt = 0; nt < 4; nt++) {
                const float* b = &BS(smem, p, wn + nt * 8 + ly, k0 + lx);
                bf[nt][0] = __float_as_uint(b[0]);
                bf[nt][1] = __float_as_uint(b[4]);
            }
#pragma unroll
            for (int mt = 0; mt < 4; mt++)
#pragma unroll
                for (int nt = 0; nt < 4; nt++)
                    mma_tf32(acc[mt][nt][0], acc[mt][nt][1], acc[mt][nt][2], acc[mt][nt][3],
                             af[mt][0], af[mt][1], af[mt][2], af[mt][3],
                             bf[nt][0], bf[nt][1]);
        }
        __syncthreads();
    }

#pragma unroll
    for (int mt = 0; mt < 4; mt++) {
        int row = row0 + wm + mt * 16 + ly;
#pragma unroll
        for (int nt = 0; nt < 4; nt++) {
            int col = col0 + wn + nt * 8 + 2 * lx;
            float b0 = bias[col], b1 = bias[col + 1];
            float2 v0 = {acc[mt][nt][0] + b0, acc[mt][nt][1] + b1};
            float2 v1 = {acc[mt][nt][2] + b0, acc[mt][nt][3] + b1};
            *(float2*)(out + (size_t)row * OUT_D + col) = v0;
            *(float2*)(out + (size_t)(row + 8) * OUT_D + col) = v1;
        }
    }
}

// ---------------------------------------------------------------- launch
extern "C" void kernel_launch(void* const* d_in, const int* in_sizes, int n_in,
                              void* d_out, int out_size)
{
    const float* x    = (const float*)d_in[0];
    const float* wm   = (const float*)d_in[1];
    const float* bias = (const float*)d_in[2];
    const float* U    = (const float*)d_in[3];
    const float* S    = (const float*)d_in[4];
    const float* V    = (const float*)d_in[5];
    const float* Wg1  = (const float*)d_in[6];
    const float* bg1  = (const float*)d_in[7];
    const float* Wg2  = (const float*)d_in[8];
    const float* bg2  = (const float*)d_in[9];
    float* out = (float*)d_out;

    cudaFuncSetAttribute(k_proj_mma, cudaFuncAttributeMaxDynamicSharedMemorySize, SMEM_BYTES);
    cudaFuncSetAttribute(k_main_mma, cudaFuncAttributeMaxDynamicSharedMemorySize, SMEM_BYTES);

    k_tr<<<dim3(HG_N / 32, IN_D / 32), dim3(32, 32)>>>(Wg1);

    k_proj_mma<<<dim3(3, N_TOK / BM), NTHR, SMEM_BYTES>>>(x, V, bg1);

    k_gate<<<N_TOK / 8, 256>>>(Wg2, bg2, S);

    k_main_mma<<<dim3(OUT_D / BN, N_TOK / BM), NTHR, SMEM_BYTES>>>(x, wm, U, bias, out);
}

// round 5
// speedup vs baseline: 3.8105x; 1.0919x over previous
#include <cuda_runtime.h>
#include <cstdint>
#include <math.h>

// ---------------------------------------------------------------- constants
#define N_TOK 4096
#define IN_D  1024
#define OUT_D 1024
#define E_N   8
#define R_N   16
#define HG_N  256
#define ER_N  128

// scratch (no allocation allowed) — tf32-pre-rounded copies
__device__ float g_H[(size_t)N_TOK * HG_N];      // 4 MB hidden acts
__device__ float g_C[(size_t)N_TOK * ER_N];      // 2 MB coeffs (rounded by k_gate)
__device__ float g_Xr[(size_t)N_TOK * IN_D];     // 16 MB
__device__ float g_Wmr[(size_t)OUT_D * IN_D];    // 4 MB
__device__ float g_Ur[(size_t)E_N * OUT_D * R_N];// 0.5 MB
__device__ float g_Vr[(size_t)E_N * R_N * IN_D]; // 0.5 MB
__device__ float g_Wg1T[(size_t)HG_N * IN_D];    // 1 MB transposed+rounded

// ---------------------------------------------------------------- helpers
__device__ __forceinline__ uint32_t tf32r(float x) {
    uint32_t r; asm("cvt.rna.tf32.f32 %0, %1;" : "=r"(r) : "f"(x)); return r;
}
__device__ __forceinline__ float tf32rf(float x) { return __uint_as_float(tf32r(x)); }

__device__ __forceinline__ uint32_t smem_u32(const void* p) {
    uint32_t a;
    asm("{ .reg .u64 t; cvta.to.shared.u64 t, %1; cvt.u32.u64 %0, t; }"
        : "=r"(a) : "l"(p));
    return a;
}
__device__ __forceinline__ void cp16(uint32_t dst, const void* src) {
    asm volatile("cp.async.cg.shared.global [%0], [%1], 16;"
                 :: "r"(dst), "l"(src));
}
#define CP_COMMIT() asm volatile("cp.async.commit_group;" ::: "memory")
#define CP_WAIT(n)  asm volatile("cp.async.wait_group %0;" :: "n"(n) : "memory")

__device__ __forceinline__ void mma_tf32(float& d0, float& d1, float& d2, float& d3,
                                         uint32_t a0, uint32_t a1, uint32_t a2, uint32_t a3,
                                         uint32_t b0, uint32_t b1) {
    asm volatile(
        "mma.sync.aligned.m16n8k8.row.col.f32.tf32.tf32.f32 "
        "{%0,%1,%2,%3}, {%4,%5,%6,%7}, {%8,%9}, {%0,%1,%2,%3};"
        : "+f"(d0), "+f"(d1), "+f"(d2), "+f"(d3)
        : "r"(a0), "r"(a1), "r"(a2), "r"(a3), "r"(b0), "r"(b1));
}

// ---------------------------------------------------------------- tiling
#define BM   128
#define BN   128
#define BK   32
#define BKP  36                       // padded (conflict-free, 16B-aligned rows)
#define NTHR 256
#define ASTRIDE (BM * BKP)
#define BSTRIDE (BN * BKP)
#define SMEM_BYTES ((2 * ASTRIDE + 2 * BSTRIDE) * 4)   // 73728

#define A_OFF(p, m, k) ((((p) * BM + (m)) * BKP + (k)))
#define B_OFF(p, n, k) ((2 * ASTRIDE + ((p) * BN + (n)) * BKP + (k)))

// ---------------------------------------------------------------- prep
__global__ void k_round(const float* __restrict__ src, float* __restrict__ dst,
                        int n4) {
    int i = blockIdx.x * blockDim.x + threadIdx.x;
    if (i < n4) {
        float4 v = ((const float4*)src)[i];
        v.x = tf32rf(v.x); v.y = tf32rf(v.y); v.z = tf32rf(v.z); v.w = tf32rf(v.w);
        ((float4*)dst)[i] = v;
    }
}

__global__ void k_tr(const float* __restrict__ Wg1) {
    __shared__ float t[32][33];
    int bx = blockIdx.x * 32;   // hg
    int by = blockIdx.y * 32;   // in
    int x = threadIdx.x, y = threadIdx.y;
    t[y][x] = Wg1[(size_t)(by + y) * HG_N + bx + x];
    __syncthreads();
    g_Wg1T[(size_t)(bx + y) * IN_D + by + x] = tf32rf(t[x][y]);
}

// ---------------------------------------------------------------- K1: proj
// bx 0,1 -> H = relu(X@Wg1 + bg1);  bx 2 -> T = X@V^T -> g_C (unrounded; k_gate rounds)
__global__ void __launch_bounds__(NTHR, 2) k_proj_mma(
    const float* __restrict__ bg1)
{
    extern __shared__ float smem[];
    const uint32_t sb = smem_u32(smem);
    const int tid = threadIdx.x, wid = tid >> 5, lane = tid & 31;
    const int ly = lane >> 2, lx = lane & 3;
    const int bx = blockIdx.x;
    const int row0 = blockIdx.y * BM;
    const int wm = (wid & 1) * 64;
    const int wn = (wid >> 1) * 32;
    const float* Bsrc = (bx < 2) ? (g_Wg1T + (size_t)bx * BN * IN_D) : g_Vr;

    float acc[4][4][4];
#pragma unroll
    for (int mt = 0; mt < 4; mt++)
#pragma unroll
        for (int nt = 0; nt < 4; nt++)
#pragma unroll
            for (int r = 0; r < 4; r++) acc[mt][nt][r] = 0.f;

    auto issueCp = [&](int p, int k0) {
#pragma unroll
        for (int q = 0; q < 4; q++) {
            int u = tid + q * NTHR, m = u >> 3, kc = (u & 7) << 2;
            cp16(sb + A_OFF(p, m, kc) * 4, g_Xr + (size_t)(row0 + m) * IN_D + k0 + kc);
        }
#pragma unroll
        for (int q = 0; q < 4; q++) {
            int u = tid + q * NTHR, n = u >> 3, kc = (u & 7) << 2;
            cp16(sb + B_OFF(p, n, kc) * 4, Bsrc + (size_t)n * IN_D + k0 + kc);
        }
        CP_COMMIT();
    };

    const int NT = IN_D / BK;   // 32
    issueCp(0, 0);
    for (int i = 0; i < NT; i++) {
        int p = i & 1;
        if (i + 1 < NT) { issueCp(p ^ 1, (i + 1) * BK); CP_WAIT(1); }
        else            { CP_WAIT(0); }
        __syncthreads();
#pragma unroll
        for (int ks = 0; ks < 4; ks++) {
            const int k0 = ks * 8;
            uint32_t af[4][4], bf[4][2];
#pragma unroll
            for (int mt = 0; mt < 4; mt++) {
                const float* a = &smem[A_OFF(p, wm + mt * 16 + ly, k0 + lx)];
                af[mt][0] = __float_as_uint(a[0]);
                af[mt][1] = __float_as_uint(a[8 * BKP]);
                af[mt][2] = __float_as_uint(a[4]);
                af[mt][3] = __float_as_uint(a[8 * BKP + 4]);
            }
#pragma unroll
            for (int nt = 0; nt < 4; nt++) {
                const float* b = &smem[B_OFF(p, wn + nt * 8 + ly, k0 + lx)];
                bf[nt][0] = __float_as_uint(b[0]);
                bf[nt][1] = __float_as_uint(b[4]);
            }
#pragma unroll
            for (int mt = 0; mt < 4; mt++)
#pragma unroll
                for (int nt = 0; nt < 4; nt++)
                    mma_tf32(acc[mt][nt][0], acc[mt][nt][1], acc[mt][nt][2], acc[mt][nt][3],
                             af[mt][0], af[mt][1], af[mt][2], af[mt][3],
                             bf[nt][0], bf[nt][1]);
        }
        __syncthreads();
    }

#pragma unroll
    for (int mt = 0; mt < 4; mt++) {
        int row = row0 + wm + mt * 16 + ly;
#pragma unroll
        for (int nt = 0; nt < 4; nt++) {
            int col = wn + nt * 8 + 2 * lx;
            if (bx < 2) {
                int colh = bx * BN + col;
                float b0 = bg1[colh], b1 = bg1[colh + 1];
                float2 v0, v1;
                v0.x = fmaxf(acc[mt][nt][0] + b0, 0.f);
                v0.y = fmaxf(acc[mt][nt][1] + b1, 0.f);
                v1.x = fmaxf(acc[mt][nt][2] + b0, 0.f);
                v1.y = fmaxf(acc[mt][nt][3] + b1, 0.f);
                *(float2*)(g_H + (size_t)row * HG_N + colh) = v0;
                *(float2*)(g_H + (size_t)(row + 8) * HG_N + colh) = v1;
            } else {
                float2 v0 = {acc[mt][nt][0], acc[mt][nt][1]};
                float2 v1 = {acc[mt][nt][2], acc[mt][nt][3]};
                *(float2*)(g_C + (size_t)row * ER_N + col) = v0;
                *(float2*)(g_C + (size_t)(row + 8) * ER_N + col) = v1;
            }
        }
    }
}

// ---------------------------------------------------------------- K2: gate
__global__ void __launch_bounds__(256) k_gate(
    const float* __restrict__ Wg2, const float* __restrict__ bg2,
    const float* __restrict__ S)
{
    const int warp = threadIdx.x >> 5;
    const int lane = threadIdx.x & 31;
    const int n = blockIdx.x * 8 + warp;
    if (n >= N_TOK) return;

    float acc[E_N];
#pragma unroll
    for (int e = 0; e < E_N; e++) acc[e] = 0.f;

    const float* h = g_H + (size_t)n * HG_N;
    for (int hh = lane; hh < HG_N; hh += 32) {
        float hv = h[hh];
        const float* w = Wg2 + (size_t)hh * E_N;
#pragma unroll
        for (int e = 0; e < E_N; e++) acc[e] = fmaf(hv, w[e], acc[e]);
    }
#pragma unroll
    for (int e = 0; e < E_N; e++) {
#pragma unroll
        for (int off = 16; off; off >>= 1)
            acc[e] += __shfl_xor_sync(0xffffffffu, acc[e], off);
        acc[e] += bg2[e];
    }

    int i0 = 0; float v0 = acc[0];
#pragma unroll
    for (int e = 1; e < E_N; e++) if (acc[e] > v0) { v0 = acc[e]; i0 = e; }
    int i1 = -1; float v1 = -3.0e38f;
#pragma unroll
    for (int e = 0; e < E_N; e++) if (e != i0 && acc[e] > v1) { v1 = acc[e]; i1 = e; }

    float e1 = expf(v1 - v0);
    float s  = 1.f + e1;
    float g0 = 1.f / s;
    float g1 = e1 / s;

    float* c = g_C + (size_t)n * ER_N;
#pragma unroll
    for (int q = 0; q < 4; q++) {
        int j = lane + q * 32;
        float t = c[j];
        int e = j >> 4, r = j & 15;
        float g = (e == i0) ? g0 : ((e == i1) ? g1 : 0.f);
        c[j] = tf32rf(g * S[e * R_N + r] * t);   // pre-rounded for K3
    }
}

// ---------------------------------------------------------------- K3: main
// out = X@Wm^T + Call@Uf + bias   (K = 1024 + 128 = 1152)
__global__ void __launch_bounds__(NTHR, 2) k_main_mma(
    const float* __restrict__ bias, float* __restrict__ out)
{
    extern __shared__ float smem[];
    const uint32_t sb = smem_u32(smem);
    const int tid = threadIdx.x, wid = tid >> 5, lane = tid & 31;
    const int ly = lane >> 2, lx = lane & 3;
    const int row0 = blockIdx.y * BM;
    const int col0 = blockIdx.x * BN;
    const int wm = (wid & 1) * 64;
    const int wn = (wid >> 1) * 32;

    float acc[4][4][4];
#pragma unroll
    for (int mt = 0; mt < 4; mt++)
#pragma unroll
        for (int nt = 0; nt < 4; nt++)
#pragma unroll
            for (int r = 0; r < 4; r++) acc[mt][nt][r] = 0.f;

    auto issueCp = [&](int p, int k0) {
        if (k0 < IN_D) {
#pragma unroll
            for (int q = 0; q < 4; q++) {
                int u = tid + q * NTHR, m = u >> 3, kc = (u & 7) << 2;
                cp16(sb + A_OFF(p, m, kc) * 4, g_Xr + (size_t)(row0 + m) * IN_D + k0 + kc);
            }
#pragma unroll
            for (int q = 0; q < 4; q++) {
                int u = tid + q * NTHR, n = u >> 3, kc = (u & 7) << 2;
                cp16(sb + B_OFF(p, n, kc) * 4, g_Wmr + (size_t)(col0 + n) * IN_D + k0 + kc);
            }
        } else {
            const int kk = k0 - IN_D;
#pragma unroll
            for (int q = 0; q < 4; q++) {
                int u = tid + q * NTHR, m = u >> 3, kc = (u & 7) << 2;
                cp16(sb + A_OFF(p, m, kc) * 4, g_C + (size_t)(row0 + m) * ER_N + kk + kc);
            }
#pragma unroll
            for (int q = 0; q < 4; q++) {
                int u = tid + q * NTHR, n = u >> 3, kc = (u & 7) << 2;
                int kg = kk + kc, e = kg >> 4, r0 = kg & 15;
                cp16(sb + B_OFF(p, n, kc) * 4,
                     g_Ur + ((size_t)e * OUT_D + (col0 + n)) * R_N + r0);
            }
        }
        CP_COMMIT();
    };

    const int NT = (IN_D + ER_N) / BK;   // 36
    issueCp(0, 0);
    for (int i = 0; i < NT; i++) {
        int p = i & 1;
        if (i + 1 < NT) { issueCp(p ^ 1, (i + 1) * BK); CP_WAIT(1); }
        else            { CP_WAIT(0); }
        __syncthreads();
#pragma unroll
        for (int ks = 0; ks < 4; ks++) {
            const int k0 = ks * 8;
            uint32_t af[4][4], bf[4][2];
#pragma unroll
            for (int mt = 0; mt < 4; mt++) {
                const float* a = &smem[A_OFF(p, wm + mt * 16 + ly, k0 + lx)];
                af[mt][0] = __float_as_uint(a[0]);
                af[mt][1] = __float_as_uint(a[8 * BKP]);
                af[mt][2] = __float_as_uint(a[4]);
                af[mt][3] = __float_as_uint(a[8 * BKP + 4]);
            }
#pragma unroll
            for (int nt = 0; nt < 4; nt++) {
                const float* b = &smem[B_OFF(p, wn + nt * 8 + ly, k0 + lx)];
                bf[nt][0] = __float_as_uint(b[0]);
                bf[nt][1] = __float_as_uint(b[4]);
            }
#pragma unroll
            for (int mt = 0; mt < 4; mt++)
#pragma unroll
                for (int nt = 0; nt < 4; nt++)
                    mma_tf32(acc[mt][nt][0], acc[mt][nt][1], acc[mt][nt][2], acc[mt][nt][3],
                             af[mt][0], af[mt][1], af[mt][2], af[mt][3],
                             bf[nt][0], bf[nt][1]);
        }
        __syncthreads();
    }

#pragma unroll
    for (int mt = 0; mt < 4; mt++) {
        int row = row0 + wm + mt * 16 + ly;
#pragma unroll
        for (int nt = 0; nt < 4; nt++) {
            int col = col0 + wn + nt * 8 + 2 * lx;
            float b0 = bias[col], b1 = bias[col + 1];
            float2 v0 = {acc[mt][nt][0] + b0, acc[mt][nt][1] + b1};
            float2 v1 = {acc[mt][nt][2] + b0, acc[mt][nt][3] + b1};
            *(float2*)(out + (size_t)row * OUT_D + col) = v0;
            *(float2*)(out + (size_t)(row + 8) * OUT_D + col) = v1;
        }
    }
}

// ---------------------------------------------------------------- launch
extern "C" void kernel_launch(void* const* d_in, const int* in_sizes, int n_in,
                              void* d_out, int out_size)
{
    const float* x    = (const float*)d_in[0];
    const float* wm   = (const float*)d_in[1];
    const float* bias = (const float*)d_in[2];
    const float* U    = (const float*)d_in[3];
    const float* S    = (const float*)d_in[4];
    const float* V    = (const float*)d_in[5];
    const float* Wg1  = (const float*)d_in[6];
    const float* bg1  = (const float*)d_in[7];
    const float* Wg2  = (const float*)d_in[8];
    const float* bg2  = (const float*)d_in[9];
    float* out = (float*)d_out;

    cudaFuncSetAttribute(k_proj_mma, cudaFuncAttributeMaxDynamicSharedMemorySize, SMEM_BYTES);
    cudaFuncSetAttribute(k_main_mma, cudaFuncAttributeMaxDynamicSharedMemorySize, SMEM_BYTES);

    // prep: tf32-round the GEMM operands once (memory-bound)
    {
        float* xr  = nullptr; float* wmr = nullptr; float* ur = nullptr; float* vr = nullptr;
        cudaGetSymbolAddress((void**)&xr,  g_Xr);
        cudaGetSymbolAddress((void**)&wmr, g_Wmr);
        cudaGetSymbolAddress((void**)&ur,  g_Ur);
        cudaGetSymbolAddress((void**)&vr,  g_Vr);
        int n4x = (N_TOK * IN_D) / 4;
        int n4w = (OUT_D * IN_D) / 4;
        int n4u = (E_N * OUT_D * R_N) / 4;
        int n4v = (E_N * R_N * IN_D) / 4;
        k_round<<<(n4x + 255) / 256, 256>>>(x,  xr,  n4x);
        k_round<<<(n4w + 255) / 256, 256>>>(wm, wmr, n4w);
        k_round<<<(n4u + 255) / 256, 256>>>(U,  ur,  n4u);
        k_round<<<(n4v + 255) / 256, 256>>>(V,  vr,  n4v);
    }

    k_tr<<<dim3(HG_N / 32, IN_D / 32), dim3(32, 32)>>>(Wg1);

    k_proj_mma<<<dim3(3, N_TOK / BM), NTHR, SMEM_BYTES>>>(bg1);

    k_gate<<<N_TOK / 8, 256>>>(Wg2, bg2, S);

    k_main_mma<<<dim3(OUT_D / BN, N_TOK / BM), NTHR, SMEM_BYTES>>>(bias, out);
}

// round 6
// speedup vs baseline: 3.8924x; 1.0215x over previous
#include <cuda_runtime.h>
#include <cstdint>
#include <math.h>

// ---------------------------------------------------------------- constants
#define N_TOK 4096
#define IN_D  1024
#define OUT_D 1024
#define E_N   8
#define R_N   16
#define HG_N  256
#define ER_N  128

// scratch (no allocation allowed) — tf32-pre-rounded copies
__device__ float g_H[(size_t)N_TOK * HG_N];      // 4 MB hidden acts
__device__ float g_C[(size_t)N_TOK * ER_N];      // 2 MB coeffs (rounded by k_gate)
__device__ float g_Xr[(size_t)N_TOK * IN_D];     // 16 MB
__device__ float g_Wmr[(size_t)OUT_D * IN_D];    // 4 MB
__device__ float g_Ur[(size_t)E_N * OUT_D * R_N];// 0.5 MB
__device__ float g_Vr[(size_t)E_N * R_N * IN_D]; // 0.5 MB
__device__ float g_Wg1T[(size_t)HG_N * IN_D];    // 1 MB transposed+rounded

// ---------------------------------------------------------------- helpers
__device__ __forceinline__ uint32_t tf32r(float x) {
    uint32_t r; asm("cvt.rna.tf32.f32 %0, %1;" : "=r"(r) : "f"(x)); return r;
}
__device__ __forceinline__ float tf32rf(float x) { return __uint_as_float(tf32r(x)); }

__device__ __forceinline__ uint32_t smem_u32(const void* p) {
    uint32_t a;
    asm("{ .reg .u64 t; cvta.to.shared.u64 t, %1; cvt.u32.u64 %0, t; }"
        : "=r"(a) : "l"(p));
    return a;
}
__device__ __forceinline__ void cp16(uint32_t dst, const void* src) {
    asm volatile("cp.async.cg.shared.global [%0], [%1], 16;"
                 :: "r"(dst), "l"(src));
}
#define CP_COMMIT() asm volatile("cp.async.commit_group;" ::: "memory")
#define CP_WAIT(n)  asm volatile("cp.async.wait_group %0;" :: "n"(n) : "memory")

__device__ __forceinline__ void mma_tf32(float& d0, float& d1, float& d2, float& d3,
                                         uint32_t a0, uint32_t a1, uint32_t a2, uint32_t a3,
                                         uint32_t b0, uint32_t b1) {
    asm volatile(
        "mma.sync.aligned.m16n8k8.row.col.f32.tf32.tf32.f32 "
        "{%0,%1,%2,%3}, {%4,%5,%6,%7}, {%8,%9}, {%0,%1,%2,%3};"
        : "+f"(d0), "+f"(d1), "+f"(d2), "+f"(d3)
        : "r"(a0), "r"(a1), "r"(a2), "r"(a3), "r"(b0), "r"(b1));
}

// ---------------------------------------------------------------- tiling
#define BM   128
#define BN   128
#define BK   32
#define BKP  36                       // padded (conflict-free, 16B-aligned rows)
#define SST  3                        // pipeline stages
#define NTHR 256
#define ASTRIDE (BM * BKP)
#define BSTRIDE (BN * BKP)
#define SMEM_BYTES (SST * (ASTRIDE + BSTRIDE) * 4)   // 110592

#define A_OFF(p, m, k) (((p) * BM + (m)) * BKP + (k))
#define B_OFF(p, n, k) (SST * ASTRIDE + ((p) * BN + (n)) * BKP + (k))

// ---------------------------------------------------------------- prep (single fused launch)
#define NX4 ((N_TOK * IN_D) / 4)
#define NW4 ((OUT_D * IN_D) / 4)
#define NU4 ((E_N * OUT_D * R_N) / 4)
#define NV4 ((E_N * R_N * IN_D) / 4)
#define NTOT4 (NX4 + NW4 + NU4 + NV4)

__global__ void k_round_all(const float* __restrict__ x, const float* __restrict__ wm,
                            const float* __restrict__ U, const float* __restrict__ V) {
    int i = blockIdx.x * blockDim.x + threadIdx.x;
    if (i >= NTOT4) return;
    const float4* src; float4* dst; int j = i;
    if (j < NX4)                      { src = (const float4*)x;  dst = (float4*)g_Xr; }
    else if ((j -= NX4) < NW4)        { src = (const float4*)wm; dst = (float4*)g_Wmr; }
    else if ((j -= NW4) < NU4)        { src = (const float4*)U;  dst = (float4*)g_Ur; }
    else { j -= NU4;                    src = (const float4*)V;  dst = (float4*)g_Vr; }
    float4 v = src[j];
    v.x = tf32rf(v.x); v.y = tf32rf(v.y); v.z = tf32rf(v.z); v.w = tf32rf(v.w);
    dst[j] = v;
}

__global__ void k_tr(const float* __restrict__ Wg1) {
    __shared__ float t[32][33];
    int bx = blockIdx.x * 32;   // hg
    int by = blockIdx.y * 32;   // in
    int x = threadIdx.x, y = threadIdx.y;
    t[y][x] = Wg1[(size_t)(by + y) * HG_N + bx + x];
    __syncthreads();
    g_Wg1T[(size_t)(bx + y) * IN_D + by + x] = tf32rf(t[x][y]);
}

// ---------------------------------------------------------------- K1: proj
// bx 0,1 -> H = relu(X@Wg1 + bg1);  bx 2 -> T = X@V^T -> g_C
__global__ void __launch_bounds__(NTHR, 2) k_proj_mma(
    const float* __restrict__ bg1)
{
    extern __shared__ float smem[];
    const uint32_t sb = smem_u32(smem);
    const int tid = threadIdx.x, wid = tid >> 5, lane = tid & 31;
    const int ly = lane >> 2, lx = lane & 3;
    const int bx = blockIdx.x;
    const int row0 = blockIdx.y * BM;
    const int wm = (wid & 1) * 64;
    const int wn = (wid >> 1) * 32;
    const float* Bsrc = (bx < 2) ? (g_Wg1T + (size_t)bx * BN * IN_D) : g_Vr;

    float acc[4][4][4];
#pragma unroll
    for (int mt = 0; mt < 4; mt++)
#pragma unroll
        for (int nt = 0; nt < 4; nt++)
#pragma unroll
            for (int r = 0; r < 4; r++) acc[mt][nt][r] = 0.f;

    auto issueCp = [&](int p, int k0) {
#pragma unroll
        for (int q = 0; q < 4; q++) {
            int u = tid + q * NTHR, m = u >> 3, kc = (u & 7) << 2;
            cp16(sb + A_OFF(p, m, kc) * 4, g_Xr + (size_t)(row0 + m) * IN_D + k0 + kc);
        }
#pragma unroll
        for (int q = 0; q < 4; q++) {
            int u = tid + q * NTHR, n = u >> 3, kc = (u & 7) << 2;
            cp16(sb + B_OFF(p, n, kc) * 4, Bsrc + (size_t)n * IN_D + k0 + kc);
        }
        CP_COMMIT();
    };

    const int NT = IN_D / BK;   // 32
    issueCp(0, 0);
    issueCp(1, BK);
    for (int i = 0; i < NT; i++) {
        const int p = i % SST;
        if (i + 1 < NT) { CP_WAIT(1); } else { CP_WAIT(0); }
        __syncthreads();
        if (i + 2 < NT) issueCp((i + 2) % SST, (i + 2) * BK);
#pragma unroll
        for (int ks = 0; ks < 4; ks++) {
            const int k0 = ks * 8;
            uint32_t af[4][4], bf[4][2];
#pragma unroll
            for (int mt = 0; mt < 4; mt++) {
                const float* a = &smem[A_OFF(p, wm + mt * 16 + ly, k0 + lx)];
                af[mt][0] = __float_as_uint(a[0]);
                af[mt][1] = __float_as_uint(a[8 * BKP]);
                af[mt][2] = __float_as_uint(a[4]);
                af[mt][3] = __float_as_uint(a[8 * BKP + 4]);
            }
#pragma unroll
            for (int nt = 0; nt < 4; nt++) {
                const float* b = &smem[B_OFF(p, wn + nt * 8 + ly, k0 + lx)];
                bf[nt][0] = __float_as_uint(b[0]);
                bf[nt][1] = __float_as_uint(b[4]);
            }
#pragma unroll
            for (int mt = 0; mt < 4; mt++)
#pragma unroll
                for (int nt = 0; nt < 4; nt++)
                    mma_tf32(acc[mt][nt][0], acc[mt][nt][1], acc[mt][nt][2], acc[mt][nt][3],
                             af[mt][0], af[mt][1], af[mt][2], af[mt][3],
                             bf[nt][0], bf[nt][1]);
        }
    }

#pragma unroll
    for (int mt = 0; mt < 4; mt++) {
        int row = row0 + wm + mt * 16 + ly;
#pragma unroll
        for (int nt = 0; nt < 4; nt++) {
            int col = wn + nt * 8 + 2 * lx;
            if (bx < 2) {
                int colh = bx * BN + col;
                float b0 = bg1[colh], b1 = bg1[colh + 1];
                float2 v0, v1;
                v0.x = fmaxf(acc[mt][nt][0] + b0, 0.f);
                v0.y = fmaxf(acc[mt][nt][1] + b1, 0.f);
                v1.x = fmaxf(acc[mt][nt][2] + b0, 0.f);
                v1.y = fmaxf(acc[mt][nt][3] + b1, 0.f);
                *(float2*)(g_H + (size_t)row * HG_N + colh) = v0;
                *(float2*)(g_H + (size_t)(row + 8) * HG_N + colh) = v1;
            } else {
                float2 v0 = {acc[mt][nt][0], acc[mt][nt][1]};
                float2 v1 = {acc[mt][nt][2], acc[mt][nt][3]};
                *(float2*)(g_C + (size_t)row * ER_N + col) = v0;
                *(float2*)(g_C + (size_t)(row + 8) * ER_N + col) = v1;
            }
        }
    }
}

// ---------------------------------------------------------------- K2: gate
__global__ void __launch_bounds__(256) k_gate(
    const float* __restrict__ Wg2, const float* __restrict__ bg2,
    const float* __restrict__ S)
{
    const int warp = threadIdx.x >> 5;
    const int lane = threadIdx.x & 31;
    const int n = blockIdx.x * 8 + warp;
    if (n >= N_TOK) return;

    float acc[E_N];
#pragma unroll
    for (int e = 0; e < E_N; e++) acc[e] = 0.f;

    const float* h = g_H + (size_t)n * HG_N;
    for (int hh = lane; hh < HG_N; hh += 32) {
        float hv = h[hh];
        const float* w = Wg2 + (size_t)hh * E_N;
#pragma unroll
        for (int e = 0; e < E_N; e++) acc[e] = fmaf(hv, w[e], acc[e]);
    }
#pragma unroll
    for (int e = 0; e < E_N; e++) {
#pragma unroll
        for (int off = 16; off; off >>= 1)
            acc[e] += __shfl_xor_sync(0xffffffffu, acc[e], off);
        acc[e] += bg2[e];
    }

    int i0 = 0; float v0 = acc[0];
#pragma unroll
    for (int e = 1; e < E_N; e++) if (acc[e] > v0) { v0 = acc[e]; i0 = e; }
    int i1 = -1; float v1 = -3.0e38f;
#pragma unroll
    for (int e = 0; e < E_N; e++) if (e != i0 && acc[e] > v1) { v1 = acc[e]; i1 = e; }

    float e1 = expf(v1 - v0);
    float s  = 1.f + e1;
    float g0 = 1.f / s;
    float g1 = e1 / s;

    float* c = g_C + (size_t)n * ER_N;
#pragma unroll
    for (int q = 0; q < 4; q++) {
        int j = lane + q * 32;
        float t = c[j];
        int e = j >> 4, r = j & 15;
        float g = (e == i0) ? g0 : ((e == i1) ? g1 : 0.f);
        c[j] = tf32rf(g * S[e * R_N + r] * t);   // pre-rounded for K3
    }
}

// ---------------------------------------------------------------- K3: main
// out = X@Wm^T + Call@Uf + bias   (K = 1024 + 128 = 1152)
__global__ void __launch_bounds__(NTHR, 2) k_main_mma(
    const float* __restrict__ bias, float* __restrict__ out)
{
    extern __shared__ float smem[];
    const uint32_t sb = smem_u32(smem);
    const int tid = threadIdx.x, wid = tid >> 5, lane = tid & 31;
    const int ly = lane >> 2, lx = lane & 3;
    const int row0 = blockIdx.y * BM;
    const int col0 = blockIdx.x * BN;
    const int wm = (wid & 1) * 64;
    const int wn = (wid >> 1) * 32;

    float acc[4][4][4];
#pragma unroll
    for (int mt = 0; mt < 4; mt++)
#pragma unroll
        for (int nt = 0; nt < 4; nt++)
#pragma unroll
            for (int r = 0; r < 4; r++) acc[mt][nt][r] = 0.f;

    auto issueCp = [&](int p, int k0) {
        if (k0 < IN_D) {
#pragma unroll
            for (int q = 0; q < 4; q++) {
                int u = tid + q * NTHR, m = u >> 3, kc = (u & 7) << 2;
                cp16(sb + A_OFF(p, m, kc) * 4, g_Xr + (size_t)(row0 + m) * IN_D + k0 + kc);
            }
#pragma unroll
            for (int q = 0; q < 4; q++) {
                int u = tid + q * NTHR, n = u >> 3, kc = (u & 7) << 2;
                cp16(sb + B_OFF(p, n, kc) * 4, g_Wmr + (size_t)(col0 + n) * IN_D + k0 + kc);
            }
        } else {
            const int kk = k0 - IN_D;
#pragma unroll
            for (int q = 0; q < 4; q++) {
                int u = tid + q * NTHR, m = u >> 3, kc = (u & 7) << 2;
                cp16(sb + A_OFF(p, m, kc) * 4, g_C + (size_t)(row0 + m) * ER_N + kk + kc);
            }
#pragma unroll
            for (int q = 0; q < 4; q++) {
                int u = tid + q * NTHR, n = u >> 3, kc = (u & 7) << 2;
                int kg = kk + kc, e = kg >> 4, r0 = kg & 15;
                cp16(sb + B_OFF(p, n, kc) * 4,
                     g_Ur + ((size_t)e * OUT_D + (col0 + n)) * R_N + r0);
            }
        }
        CP_COMMIT();
    };

    const int NT = (IN_D + ER_N) / BK;   // 36
    issueCp(0, 0);
    issueCp(1, BK);
    for (int i = 0; i < NT; i++) {
        const int p = i % SST;
        if (i + 1 < NT) { CP_WAIT(1); } else { CP_WAIT(0); }
        __syncthreads();
        if (i + 2 < NT) issueCp((i + 2) % SST, (i + 2) * BK);
#pragma unroll
        for (int ks = 0; ks < 4; ks++) {
            const int k0 = ks * 8;
            uint32_t af[4][4], bf[4][2];
#pragma unroll
            for (int mt = 0; mt < 4; mt++) {
                const float* a = &smem[A_OFF(p, wm + mt * 16 + ly, k0 + lx)];
                af[mt][0] = __float_as_uint(a[0]);
                af[mt][1] = __float_as_uint(a[8 * BKP]);
                af[mt][2] = __float_as_uint(a[4]);
                af[mt][3] = __float_as_uint(a[8 * BKP + 4]);
            }
#pragma unroll
            for (int nt = 0; nt < 4; nt++) {
                const float* b = &smem[B_OFF(p, wn + nt * 8 + ly, k0 + lx)];
                bf[nt][0] = __float_as_uint(b[0]);
                bf[nt][1] = __float_as_uint(b[4]);
            }
#pragma unroll
            for (int mt = 0; mt < 4; mt++)
#pragma unroll
                for (int nt = 0; nt < 4; nt++)
                    mma_tf32(acc[mt][nt][0], acc[mt][nt][1], acc[mt][nt][2], acc[mt][nt][3],
                             af[mt][0], af[mt][1], af[mt][2], af[mt][3],
                             bf[nt][0], bf[nt][1]);
        }
    }

#pragma unroll
    for (int mt = 0; mt < 4; mt++) {
        int row = row0 + wm + mt * 16 + ly;
#pragma unroll
        for (int nt = 0; nt < 4; nt++) {
            int col = col0 + wn + nt * 8 + 2 * lx;
            float b0 = bias[col], b1 = bias[col + 1];
            float2 v0 = {acc[mt][nt][0] + b0, acc[mt][nt][1] + b1};
            float2 v1 = {acc[mt][nt][2] + b0, acc[mt][nt][3] + b1};
            *(float2*)(out + (size_t)row * OUT_D + col) = v0;
            *(float2*)(out + (size_t)(row + 8) * OUT_D + col) = v1;
        }
    }
}

// ---------------------------------------------------------------- launch
extern "C" void kernel_launch(void* const* d_in, const int* in_sizes, int n_in,
                              void* d_out, int out_size)
{
    const float* x    = (const float*)d_in[0];
    const float* wm   = (const float*)d_in[1];
    const float* bias = (const float*)d_in[2];
    const float* U    = (const float*)d_in[3];
    const float* S    = (const float*)d_in[4];
    const float* V    = (const float*)d_in[5];
    const float* Wg1  = (const float*)d_in[6];
    const float* bg1  = (const float*)d_in[7];
    const float* Wg2  = (const float*)d_in[8];
    const float* bg2  = (const float*)d_in[9];
    float* out = (float*)d_out;

    cudaFuncSetAttribute(k_proj_mma, cudaFuncAttributeMaxDynamicSharedMemorySize, SMEM_BYTES);
    cudaFuncSetAttribute(k_main_mma, cudaFuncAttributeMaxDynamicSharedMemorySize, SMEM_BYTES);

    // single fused prep launch: tf32-round X, Wm, U, V
    k_round_all<<<(NTOT4 + 255) / 256, 256>>>(x, wm, U, V);

    k_tr<<<dim3(HG_N / 32, IN_D / 32), dim3(32, 32)>>>(Wg1);

    k_proj_mma<<<dim3(3, N_TOK / BM), NTHR, SMEM_BYTES>>>(bg1);

    k_gate<<<N_TOK / 8, 256>>>(Wg2, bg2, S);

    k_main_mma<<<dim3(OUT_D / BN, N_TOK / BM), NTHR, SMEM_BYTES>>>(bias, out);
}

// round 7
// speedup vs baseline: 4.1703x; 1.0714x over previous
#include <cuda_runtime.h>
#include <cstdint>
#include <math.h>

// ---------------------------------------------------------------- constants
#define N_TOK 4096
#define IN_D  1024
#define OUT_D 1024
#define E_N   8
#define R_N   16
#define HG_N  256
#define ER_N  128

// scratch (no allocation allowed)
__device__ float g_C[(size_t)N_TOK * ER_N];       // 2 MB coeffs
__device__ float g_Wmr[(size_t)OUT_D * IN_D];     // 4 MB rounded Wm
__device__ float g_Ur[(size_t)E_N * OUT_D * R_N]; // 0.5 MB rounded U
__device__ float g_Vr[(size_t)E_N * R_N * IN_D];  // 0.5 MB rounded V
__device__ float g_Wg1T[(size_t)HG_N * IN_D];     // 1 MB transposed+rounded
__device__ float g_logits[(size_t)N_TOK * E_N];   // 128 KB gate logits

// ---------------------------------------------------------------- helpers
__device__ __forceinline__ uint32_t tf32r(float x) {
    uint32_t r; asm("cvt.rna.tf32.f32 %0, %1;" : "=r"(r) : "f"(x)); return r;
}
__device__ __forceinline__ float tf32rf(float x) { return __uint_as_float(tf32r(x)); }

__device__ __forceinline__ uint32_t smem_u32(const void* p) {
    uint32_t a;
    asm("{ .reg .u64 t; cvta.to.shared.u64 t, %1; cvt.u32.u64 %0, t; }"
        : "=r"(a) : "l"(p));
    return a;
}
__device__ __forceinline__ void cp16(uint32_t dst, const void* src) {
    asm volatile("cp.async.cg.shared.global [%0], [%1], 16;"
                 :: "r"(dst), "l"(src));
}
#define CP_COMMIT() asm volatile("cp.async.commit_group;" ::: "memory")
#define CP_WAIT(n)  asm volatile("cp.async.wait_group %0;" :: "n"(n) : "memory")

__device__ __forceinline__ void mma_tf32(float& d0, float& d1, float& d2, float& d3,
                                         uint32_t a0, uint32_t a1, uint32_t a2, uint32_t a3,
                                         uint32_t b0, uint32_t b1) {
    asm volatile(
        "mma.sync.aligned.m16n8k8.row.col.f32.tf32.tf32.f32 "
        "{%0,%1,%2,%3}, {%4,%5,%6,%7}, {%8,%9}, {%0,%1,%2,%3};"
        : "+f"(d0), "+f"(d1), "+f"(d2), "+f"(d3)
        : "r"(a0), "r"(a1), "r"(a2), "r"(a3), "r"(b0), "r"(b1));
}

// ---------------------------------------------------------------- tiling
#define BM   128
#define BN   128
#define BK   32
#define BKP  36
#define SST  3
#define NTHR 256
#define ASTRIDE (BM * BKP)
#define BSTRIDE (BN * BKP)
#define SMEM_BYTES (SST * (ASTRIDE + BSTRIDE) * 4)   // 110592

#define A_OFF(p, m, k) (((p) * BM + (m)) * BKP + (k))
#define B_OFF(p, n, k) (SST * ASTRIDE + ((p) * BN + (n)) * BKP + (k))

// ---------------------------------------------------------------- prep (one launch)
#define NW4 ((OUT_D * IN_D) / 4)
#define NU4 ((E_N * OUT_D * R_N) / 4)
#define NV4 ((E_N * R_N * IN_D) / 4)
#define NZ4 ((N_TOK * E_N) / 4)
#define NTOT4 (NW4 + NU4 + NV4 + NZ4)
#define NB_R  (NTOT4 / 256)                 // 1312 exactly
#define NB_TR ((HG_N / 32) * (IN_D / 32))   // 256

__global__ void k_prep(const float* __restrict__ wm, const float* __restrict__ U,
                       const float* __restrict__ V, const float* __restrict__ Wg1) {
    int b = blockIdx.x;
    if (b < NB_R) {
        int i = b * 256 + threadIdx.x;
        const float4* src; float4* dst; int j = i; bool zero = false;
        if (j < NW4)               { src = (const float4*)wm; dst = (float4*)g_Wmr; }
        else if ((j -= NW4) < NU4) { src = (const float4*)U;  dst = (float4*)g_Ur; }
        else if ((j -= NU4) < NV4) { src = (const float4*)V;  dst = (float4*)g_Vr; }
        else { j -= NV4;             dst = (float4*)g_logits; zero = true; }
        if (zero) { dst[j] = make_float4(0.f, 0.f, 0.f, 0.f); return; }
        float4 v = src[j];
        v.x = tf32rf(v.x); v.y = tf32rf(v.y); v.z = tf32rf(v.z); v.w = tf32rf(v.w);
        dst[j] = v;
    } else {
        // Wg1 transpose + round: one 32x32 tile per block
        __shared__ float t[32][33];
        int tt = b - NB_R;
        int bx = (tt & 7) * 32;    // hg (HG/32 = 8)
        int by = (tt >> 3) * 32;   // in
        int x = threadIdx.x & 31, y0 = threadIdx.x >> 5;   // 8 row groups
#pragma unroll
        for (int r = 0; r < 4; r++) {
            int y = y0 + r * 8;
            t[y][x] = Wg1[(size_t)(by + y) * HG_N + bx + x];
        }
        __syncthreads();
#pragma unroll
        for (int r = 0; r < 4; r++) {
            int y = y0 + r * 8;
            g_Wg1T[(size_t)(bx + y) * IN_D + by + x] = tf32rf(t[x][y]);
        }
    }
}

// ---------------------------------------------------------------- K1: proj
// bx 0,1: h = relu(X@Wg1+bg1) -> partial logits (atomicAdd to g_logits)
// bx 2  : T = X@V^T -> g_C
__global__ void __launch_bounds__(NTHR, 2) k_proj_mma(
    const float* __restrict__ X, const float* __restrict__ bg1,
    const float* __restrict__ Wg2)
{
    extern __shared__ float smem[];
    const uint32_t sb = smem_u32(smem);
    const int tid = threadIdx.x, wid = tid >> 5, lane = tid & 31;
    const int ly = lane >> 2, lx = lane & 3;
    const int bx = blockIdx.x;
    const int row0 = blockIdx.y * BM;
    const int wm = (wid & 1) * 64;
    const int wn = (wid >> 1) * 32;
    const float* Bsrc = (bx < 2) ? (g_Wg1T + (size_t)bx * BN * IN_D) : g_Vr;

    float acc[4][4][4];
#pragma unroll
    for (int mt = 0; mt < 4; mt++)
#pragma unroll
        for (int nt = 0; nt < 4; nt++)
#pragma unroll
            for (int r = 0; r < 4; r++) acc[mt][nt][r] = 0.f;

    float4 araw[4];
    auto loadA = [&](int kt) {
        const int k0 = kt * BK;
#pragma unroll
        for (int q = 0; q < 4; q++) {
            int u = tid + q * NTHR, m = u >> 3, kc = (u & 7) << 2;
            araw[q] = *(const float4*)(X + (size_t)(row0 + m) * IN_D + k0 + kc);
        }
    };
    auto stsA = [&](int p) {
#pragma unroll
        for (int q = 0; q < 4; q++) {
            int u = tid + q * NTHR, m = u >> 3, kc = (u & 7) << 2;
            float4 v;
            v.x = tf32rf(araw[q].x); v.y = tf32rf(araw[q].y);
            v.z = tf32rf(araw[q].z); v.w = tf32rf(araw[q].w);
            *(float4*)&smem[A_OFF(p, m, kc)] = v;
        }
    };
    auto cpB = [&](int kt) {
        const int p = kt % SST, k0 = kt * BK;
#pragma unroll
        for (int q = 0; q < 4; q++) {
            int u = tid + q * NTHR, n = u >> 3, kc = (u & 7) << 2;
            cp16(sb + B_OFF(p, n, kc) * 4, Bsrc + (size_t)n * IN_D + k0 + kc);
        }
        CP_COMMIT();
    };

    const int NT = IN_D / BK;   // 32
    loadA(0); stsA(0);
    loadA(1);
    cpB(0); cpB(1);
    for (int i = 0; i < NT; i++) {
        const int p = i % SST;
        if (i + 1 < NT) { CP_WAIT(1); } else { CP_WAIT(0); }
        __syncthreads();
        if (i + 1 < NT) stsA((i + 1) % SST);
        if (i + 2 < NT) { loadA(i + 2); cpB(i + 2); }
#pragma unroll
        for (int ks = 0; ks < 4; ks++) {
            const int k0 = ks * 8;
            uint32_t af[4][4], bf[4][2];
#pragma unroll
            for (int mt = 0; mt < 4; mt++) {
                const float* a = &smem[A_OFF(p, wm + mt * 16 + ly, k0 + lx)];
                af[mt][0] = __float_as_uint(a[0]);
                af[mt][1] = __float_as_uint(a[8 * BKP]);
                af[mt][2] = __float_as_uint(a[4]);
                af[mt][3] = __float_as_uint(a[8 * BKP + 4]);
            }
#pragma unroll
            for (int nt = 0; nt < 4; nt++) {
                const float* b = &smem[B_OFF(p, wn + nt * 8 + ly, k0 + lx)];
                bf[nt][0] = __float_as_uint(b[0]);
                bf[nt][1] = __float_as_uint(b[4]);
            }
#pragma unroll
            for (int mt = 0; mt < 4; mt++)
#pragma unroll
                for (int nt = 0; nt < 4; nt++)
                    mma_tf32(acc[mt][nt][0], acc[mt][nt][1], acc[mt][nt][2], acc[mt][nt][3],
                             af[mt][0], af[mt][1], af[mt][2], af[mt][3],
                             bf[nt][0], bf[nt][1]);
        }
    }
    __syncthreads();   // smem free for epilogue reuse

    if (bx == 2) {
        // write coefficient matrix T
#pragma unroll
        for (int mt = 0; mt < 4; mt++) {
            int row = row0 + wm + mt * 16 + ly;
#pragma unroll
            for (int nt = 0; nt < 4; nt++) {
                int col = wn + nt * 8 + 2 * lx;
                float2 v0 = {acc[mt][nt][0], acc[mt][nt][1]};
                float2 v1 = {acc[mt][nt][2], acc[mt][nt][3]};
                *(float2*)(g_C + (size_t)row * ER_N + col) = v0;
                *(float2*)(g_C + (size_t)(row + 8) * ER_N + col) = v1;
            }
        }
        return;
    }

    // ---- gate-logit epilogue (bx = 0,1): h = relu(acc + bg1); logits += h @ Wg2 ----
    float* eWg2  = smem;            // [128][8] local Wg2 slice
    float* ePart = smem + 1024;     // [4][128][8] per-n-warp partials
    {
        int c = tid >> 1, half = tid & 1;   // 256 threads -> 128 cols x 2 float4
        *(float4*)&eWg2[c * 8 + half * 4] =
            *(const float4*)&Wg2[(size_t)(bx * 128 + c) * E_N + half * 4];
    }
    __syncthreads();

    const int nw = wid >> 1;
    float bgv[4][2];
#pragma unroll
    for (int nt = 0; nt < 4; nt++) {
        int colh = bx * 128 + wn + nt * 8 + 2 * lx;
        bgv[nt][0] = bg1[colh]; bgv[nt][1] = bg1[colh + 1];
    }

#pragma unroll
    for (int mt = 0; mt < 4; mt++) {
        float la0[8], la1[8];
#pragma unroll
        for (int e = 0; e < 8; e++) { la0[e] = 0.f; la1[e] = 0.f; }
#pragma unroll
        for (int nt = 0; nt < 4; nt++) {
            int c0 = wn + nt * 8 + 2 * lx;
            float h00 = fmaxf(acc[mt][nt][0] + bgv[nt][0], 0.f);
            float h01 = fmaxf(acc[mt][nt][1] + bgv[nt][1], 0.f);
            float h10 = fmaxf(acc[mt][nt][2] + bgv[nt][0], 0.f);
            float h11 = fmaxf(acc[mt][nt][3] + bgv[nt][1], 0.f);
            const float* w0 = &eWg2[c0 * 8];
            const float* w1 = &eWg2[(c0 + 1) * 8];
#pragma unroll
            for (int e = 0; e < 8; e++) {
                la0[e] = fmaf(h00, w0[e], fmaf(h01, w1[e], la0[e]));
                la1[e] = fmaf(h10, w0[e], fmaf(h11, w1[e], la1[e]));
            }
        }
        // reduce over lx lanes (bits 0-1 of lane id)
#pragma unroll
        for (int e = 0; e < 8; e++) {
            la0[e] += __shfl_xor_sync(0xffffffffu, la0[e], 1);
            la0[e] += __shfl_xor_sync(0xffffffffu, la0[e], 2);
            la1[e] += __shfl_xor_sync(0xffffffffu, la1[e], 1);
            la1[e] += __shfl_xor_sync(0xffffffffu, la1[e], 2);
        }
        if (lx == 0) {
            int r0 = wm + mt * 16 + ly;
            float* p0 = &ePart[(nw * 128 + r0) * 8];
            float* p1 = &ePart[(nw * 128 + r0 + 8) * 8];
#pragma unroll
            for (int e = 0; e < 8; e += 4) {
                *(float4*)&p0[e] = make_float4(la0[e], la0[e+1], la0[e+2], la0[e+3]);
                *(float4*)&p1[e] = make_float4(la1[e], la1[e+1], la1[e+2], la1[e+3]);
            }
        }
    }
    __syncthreads();
    // fixed-order sum of the 4 n-warp partials; one atomic per (row, e) per CTA
#pragma unroll
    for (int k = 0; k < 4; k++) {
        int idx = tid * 4 + k;          // 0..1023
        int row = idx >> 3, e = idx & 7;
        float s = ePart[(0 * 128 + row) * 8 + e];
        s += ePart[(1 * 128 + row) * 8 + e];
        s += ePart[(2 * 128 + row) * 8 + e];
        s += ePart[(3 * 128 + row) * 8 + e];
        atomicAdd(&g_logits[(size_t)(row0 + row) * E_N + e], s);
    }
}

// ---------------------------------------------------------------- K2: gate (slim)
__global__ void __launch_bounds__(256) k_gate(
    const float* __restrict__ bg2, const float* __restrict__ S)
{
    const int warp = threadIdx.x >> 5;
    const int lane = threadIdx.x & 31;
    const int n = blockIdx.x * 8 + warp;
    if (n >= N_TOK) return;

    float4 l0 = *(const float4*)&g_logits[(size_t)n * E_N];
    float4 l1 = *(const float4*)&g_logits[(size_t)n * E_N + 4];
    float4 b0 = *(const float4*)&bg2[0];
    float4 b1 = *(const float4*)&bg2[4];
    float acc[E_N] = {l0.x + b0.x, l0.y + b0.y, l0.z + b0.z, l0.w + b0.w,
                      l1.x + b1.x, l1.y + b1.y, l1.z + b1.z, l1.w + b1.w};

    int i0 = 0; float v0 = acc[0];
#pragma unroll
    for (int e = 1; e < E_N; e++) if (acc[e] > v0) { v0 = acc[e]; i0 = e; }
    int i1 = -1; float v1 = -3.0e38f;
#pragma unroll
    for (int e = 0; e < E_N; e++) if (e != i0 && acc[e] > v1) { v1 = acc[e]; i1 = e; }

    float e1 = expf(v1 - v0);
    float s  = 1.f + e1;
    float g0 = 1.f / s;
    float g1 = e1 / s;

    float* c = g_C + (size_t)n * ER_N;
#pragma unroll
    for (int q = 0; q < 4; q++) {
        int j = lane + q * 32;
        float t = c[j];
        int e = j >> 4, r = j & 15;
        float g = (e == i0) ? g0 : ((e == i1) ? g1 : 0.f);
        c[j] = tf32rf(g * S[e * R_N + r] * t);
    }
}

// ---------------------------------------------------------------- K3: main
__global__ void __launch_bounds__(NTHR, 2) k_main_mma(
    const float* __restrict__ X, const float* __restrict__ bias,
    float* __restrict__ out)
{
    extern __shared__ float smem[];
    const uint32_t sb = smem_u32(smem);
    const int tid = threadIdx.x, wid = tid >> 5, lane = tid & 31;
    const int ly = lane >> 2, lx = lane & 3;
    const int row0 = blockIdx.y * BM;
    const int col0 = blockIdx.x * BN;
    const int wm = (wid & 1) * 64;
    const int wn = (wid >> 1) * 32;

    float acc[4][4][4];
#pragma unroll
    for (int mt = 0; mt < 4; mt++)
#pragma unroll
        for (int nt = 0; nt < 4; nt++)
#pragma unroll
            for (int r = 0; r < 4; r++) acc[mt][nt][r] = 0.f;

    float4 araw[4];
    auto loadA = [&](int kt) {
        const int k0 = kt * BK;
        if (k0 < IN_D) {
#pragma unroll
            for (int q = 0; q < 4; q++) {
                int u = tid + q * NTHR, m = u >> 3, kc = (u & 7) << 2;
                araw[q] = *(const float4*)(X + (size_t)(row0 + m) * IN_D + k0 + kc);
            }
        } else {
            const int kk = k0 - IN_D;
#pragma unroll
            for (int q = 0; q < 4; q++) {
                int u = tid + q * NTHR, m = u >> 3, kc = (u & 7) << 2;
                araw[q] = *(const float4*)(g_C + (size_t)(row0 + m) * ER_N + kk + kc);
            }
        }
    };
    auto stsA = [&](int p) {
#pragma unroll
        for (int q = 0; q < 4; q++) {
            int u = tid + q * NTHR, m = u >> 3, kc = (u & 7) << 2;
            float4 v;
            v.x = tf32rf(araw[q].x); v.y = tf32rf(araw[q].y);
            v.z = tf32rf(araw[q].z); v.w = tf32rf(araw[q].w);
            *(float4*)&smem[A_OFF(p, m, kc)] = v;
        }
    };
    auto cpB = [&](int kt) {
        const int p = kt % SST, k0 = kt * BK;
        if (k0 < IN_D) {
#pragma unroll
            for (int q = 0; q < 4; q++) {
                int u = tid + q * NTHR, n = u >> 3, kc = (u & 7) << 2;
                cp16(sb + B_OFF(p, n, kc) * 4, g_Wmr + (size_t)(col0 + n) * IN_D + k0 + kc);
            }
        } else {
            const int kk = k0 - IN_D;
#pragma unroll
            for (int q = 0; q < 4; q++) {
                int u = tid + q * NTHR, n = u >> 3, kc = (u & 7) << 2;
                int kg = kk + kc, e = kg >> 4, r0 = kg & 15;
                cp16(sb + B_OFF(p, n, kc) * 4,
                     g_Ur + ((size_t)e * OUT_D + (col0 + n)) * R_N + r0);
            }
        }
        CP_COMMIT();
    };

    const int NT = (IN_D + ER_N) / BK;   // 36
    loadA(0); stsA(0);
    loadA(1);
    cpB(0); cpB(1);
    for (int i = 0; i < NT; i++) {
        const int p = i % SST;
        if (i + 1 < NT) { CP_WAIT(1); } else { CP_WAIT(0); }
        __syncthreads();
        if (i + 1 < NT) stsA((i + 1) % SST);
        if (i + 2 < NT) { loadA(i + 2); cpB(i + 2); }
#pragma unroll
        for (int ks = 0; ks < 4; ks++) {
            const int k0 = ks * 8;
            uint32_t af[4][4], bf[4][2];
#pragma unroll
            for (int mt = 0; mt < 4; mt++) {
                const float* a = &smem[A_OFF(p, wm + mt * 16 + ly, k0 + lx)];
                af[mt][0] = __float_as_uint(a[0]);
                af[mt][1] = __float_as_uint(a[8 * BKP]);
                af[mt][2] = __float_as_uint(a[4]);
                af[mt][3] = __float_as_uint(a[8 * BKP + 4]);
            }
#pragma unroll
            for (int nt = 0; nt < 4; nt++) {
                const float* b = &smem[B_OFF(p, wn + nt * 8 + ly, k0 + lx)];
                bf[nt][0] = __float_as_uint(b[0]);
                bf[nt][1] = __float_as_uint(b[4]);
            }
#pragma unroll
            for (int mt = 0; mt < 4; mt++)
#pragma unroll
                for (int nt = 0; nt < 4; nt++)
                    mma_tf32(acc[mt][nt][0], acc[mt][nt][1], acc[mt][nt][2], acc[mt][nt][3],
                             af[mt][0], af[mt][1], af[mt][2], af[mt][3],
                             bf[nt][0], bf[nt][1]);
        }
    }

#pragma unroll
    for (int mt = 0; mt < 4; mt++) {
        int row = row0 + wm + mt * 16 + ly;
#pragma unroll
        for (int nt = 0; nt < 4; nt++) {
            int col = col0 + wn + nt * 8 + 2 * lx;
            float b0 = bias[col], b1 = bias[col + 1];
            float2 v0 = {acc[mt][nt][0] + b0, acc[mt][nt][1] + b1};
            float2 v1 = {acc[mt][nt][2] + b0, acc[mt][nt][3] + b1};
            *(float2*)(out + (size_t)row * OUT_D + col) = v0;
            *(float2*)(out + (size_t)(row + 8) * OUT_D + col) = v1;
        }
    }
}

// ---------------------------------------------------------------- launch
extern "C" void kernel_launch(void* const* d_in, const int* in_sizes, int n_in,
                              void* d_out, int out_size)
{
    const float* x    = (const float*)d_in[0];
    const float* wm   = (const float*)d_in[1];
    const float* bias = (const float*)d_in[2];
    const float* U    = (const float*)d_in[3];
    const float* S    = (const float*)d_in[4];
    const float* V    = (const float*)d_in[5];
    const float* Wg1  = (const float*)d_in[6];
    const float* bg1  = (const float*)d_in[7];
    const float* Wg2  = (const float*)d_in[8];
    const float* bg2  = (const float*)d_in[9];
    float* out = (float*)d_out;

    cudaFuncSetAttribute(k_proj_mma, cudaFuncAttributeMaxDynamicSharedMemorySize, SMEM_BYTES);
    cudaFuncSetAttribute(k_main_mma, cudaFuncAttributeMaxDynamicSharedMemorySize, SMEM_BYTES);

    k_prep<<<NB_R + NB_TR, 256>>>(wm, U, V, Wg1);

    k_proj_mma<<<dim3(3, N_TOK / BM), NTHR, SMEM_BYTES>>>(x, bg1, Wg2);

    k_gate<<<N_TOK / 8, 256>>>(bg2, S);

    k_main_mma<<<dim3(OUT_D / BN, N_TOK / BM), NTHR, SMEM_BYTES>>>(x, bias, out);
}

// round 8
// speedup vs baseline: 4.2417x; 1.0171x over previous
#include <cuda_runtime.h>
#include <cstdint>
#include <math.h>

// ---------------------------------------------------------------- constants
#define N_TOK 4096
#define IN_D  1024
#define OUT_D 1024
#define E_N   8
#define R_N   16
#define HG_N  256
#define ER_N  128

// scratch (no allocation allowed)
__device__ float g_C[(size_t)N_TOK * ER_N];       // 2 MB coeffs
__device__ float g_Wmr[(size_t)OUT_D * IN_D];     // 4 MB rounded Wm
__device__ float g_Ur[(size_t)E_N * OUT_D * R_N]; // 0.5 MB rounded U
__device__ float g_Vr[(size_t)E_N * R_N * IN_D];  // 0.5 MB rounded V
__device__ float g_Wg1T[(size_t)HG_N * IN_D];     // 1 MB transposed+rounded
__device__ float g_logits[(size_t)N_TOK * E_N];   // 128 KB gate logits

// ---------------------------------------------------------------- helpers
__device__ __forceinline__ uint32_t tf32r(float x) {
    uint32_t r; asm("cvt.rna.tf32.f32 %0, %1;" : "=r"(r) : "f"(x)); return r;
}
__device__ __forceinline__ float tf32rf(float x) { return __uint_as_float(tf32r(x)); }

__device__ __forceinline__ uint32_t smem_u32(const void* p) {
    uint32_t a;
    asm("{ .reg .u64 t; cvta.to.shared.u64 t, %1; cvt.u32.u64 %0, t; }"
        : "=r"(a) : "l"(p));
    return a;
}
__device__ __forceinline__ void cp16(uint32_t dst, const void* src) {
    asm volatile("cp.async.cg.shared.global [%0], [%1], 16;"
                 :: "r"(dst), "l"(src));
}
#define CP_COMMIT() asm volatile("cp.async.commit_group;" ::: "memory")
#define CP_WAIT(n)  asm volatile("cp.async.wait_group %0;" :: "n"(n) : "memory")

__device__ __forceinline__ void ldm_x4(uint32_t& r0, uint32_t& r1,
                                       uint32_t& r2, uint32_t& r3, uint32_t addr) {
    asm volatile("ldmatrix.sync.aligned.m8n8.x4.b16 {%0,%1,%2,%3}, [%4];"
                 : "=r"(r0), "=r"(r1), "=r"(r2), "=r"(r3) : "r"(addr));
}

__device__ __forceinline__ void mma_tf32(float& d0, float& d1, float& d2, float& d3,
                                         uint32_t a0, uint32_t a1, uint32_t a2, uint32_t a3,
                                         uint32_t b0, uint32_t b1) {
    asm volatile(
        "mma.sync.aligned.m16n8k8.row.col.f32.tf32.tf32.f32 "
        "{%0,%1,%2,%3}, {%4,%5,%6,%7}, {%8,%9}, {%0,%1,%2,%3};"
        : "+f"(d0), "+f"(d1), "+f"(d2), "+f"(d3)
        : "r"(a0), "r"(a1), "r"(a2), "r"(a3), "r"(b0), "r"(b1));
}

// ---------------------------------------------------------------- tiling
#define BM   128
#define BN   128
#define BK   32
#define BKP  36
#define SST  3
#define NTHR 256
#define ASTRIDE (BM * BKP)
#define BSTRIDE (BN * BKP)
#define SMEM_BYTES (SST * (ASTRIDE + BSTRIDE) * 4)   // 110592

#define A_OFF(p, m, k) (((p) * BM + (m)) * BKP + (k))
#define B_OFF(p, n, k) (SST * ASTRIDE + ((p) * BN + (n)) * BKP + (k))

// ---------------------------------------------------------------- prep (one launch)
#define NW4 ((OUT_D * IN_D) / 4)
#define NU4 ((E_N * OUT_D * R_N) / 4)
#define NV4 ((E_N * R_N * IN_D) / 4)
#define NZ4 ((N_TOK * E_N) / 4)
#define NTOT4 (NW4 + NU4 + NV4 + NZ4)
#define NB_R  (NTOT4 / 256)                 // 1312 exactly
#define NB_TR ((HG_N / 32) * (IN_D / 32))   // 256

__global__ void k_prep(const float* __restrict__ wm, const float* __restrict__ U,
                       const float* __restrict__ V, const float* __restrict__ Wg1) {
    int b = blockIdx.x;
    if (b < NB_R) {
        int i = b * 256 + threadIdx.x;
        const float4* src; float4* dst; int j = i; bool zero = false;
        if (j < NW4)               { src = (const float4*)wm; dst = (float4*)g_Wmr; }
        else if ((j -= NW4) < NU4) { src = (const float4*)U;  dst = (float4*)g_Ur; }
        else if ((j -= NU4) < NV4) { src = (const float4*)V;  dst = (float4*)g_Vr; }
        else { j -= NV4;             dst = (float4*)g_logits; zero = true; }
        if (zero) { dst[j] = make_float4(0.f, 0.f, 0.f, 0.f); return; }
        float4 v = src[j];
        v.x = tf32rf(v.x); v.y = tf32rf(v.y); v.z = tf32rf(v.z); v.w = tf32rf(v.w);
        dst[j] = v;
    } else {
        __shared__ float t[32][33];
        int tt = b - NB_R;
        int bx = (tt & 7) * 32;    // hg
        int by = (tt >> 3) * 32;   // in
        int x = threadIdx.x & 31, y0 = threadIdx.x >> 5;
#pragma unroll
        for (int r = 0; r < 4; r++) {
            int y = y0 + r * 8;
            t[y][x] = Wg1[(size_t)(by + y) * HG_N + bx + x];
        }
        __syncthreads();
#pragma unroll
        for (int r = 0; r < 4; r++) {
            int y = y0 + r * 8;
            g_Wg1T[(size_t)(bx + y) * IN_D + by + x] = tf32rf(t[x][y]);
        }
    }
}

// ---------------------------------------------------------------- K1: proj
__global__ void __launch_bounds__(NTHR, 2) k_proj_mma(
    const float* __restrict__ X, const float* __restrict__ bg1,
    const float* __restrict__ Wg2)
{
    extern __shared__ float smem[];
    const uint32_t sb = smem_u32(smem);
    const int tid = threadIdx.x, wid = tid >> 5, lane = tid & 31;
    const int ly = lane >> 2, lx = lane & 3;
    const int bx = blockIdx.x;
    const int row0 = blockIdx.y * BM;
    const int wm = (wid & 1) * 64;
    const int wn = (wid >> 1) * 32;
    const float* Bsrc = (bx < 2) ? (g_Wg1T + (size_t)bx * BN * IN_D) : g_Vr;

    // ldmatrix per-lane source rows/cols
    const int rowA = ((lane >> 3) & 1) * 8 + (lane & 7);   // + mt*16
    const int colA = (lane >> 4) * 4;                       // + k0
    const int rowB = ((lane >> 4) & 1) * 8 + (lane & 7);   // + h*16
    const int colB = ((lane >> 3) & 1) * 4;                 // + k0
    const uint32_t aBase = sb + (uint32_t)A_OFF(0, wm + rowA, colA) * 4;
    const uint32_t bBase = sb + (uint32_t)B_OFF(0, wn + rowB, colB) * 4;

    float acc[4][4][4];
#pragma unroll
    for (int mt = 0; mt < 4; mt++)
#pragma unroll
        for (int nt = 0; nt < 4; nt++)
#pragma unroll
            for (int r = 0; r < 4; r++) acc[mt][nt][r] = 0.f;

    float4 araw[4];
    auto loadA = [&](int kt) {
        const int k0 = kt * BK;
#pragma unroll
        for (int q = 0; q < 4; q++) {
            int u = tid + q * NTHR, m = u >> 3, kc = (u & 7) << 2;
            araw[q] = *(const float4*)(X + (size_t)(row0 + m) * IN_D + k0 + kc);
        }
    };
    auto stsA = [&](int p) {
#pragma unroll
        for (int q = 0; q < 4; q++) {
            int u = tid + q * NTHR, m = u >> 3, kc = (u & 7) << 2;
            float4 v;
            v.x = tf32rf(araw[q].x); v.y = tf32rf(araw[q].y);
            v.z = tf32rf(araw[q].z); v.w = tf32rf(araw[q].w);
            *(float4*)&smem[A_OFF(p, m, kc)] = v;
        }
    };
    auto cpB = [&](int kt) {
        const int p = kt % SST, k0 = kt * BK;
#pragma unroll
        for (int q = 0; q < 4; q++) {
            int u = tid + q * NTHR, n = u >> 3, kc = (u & 7) << 2;
            cp16(sb + B_OFF(p, n, kc) * 4, Bsrc + (size_t)n * IN_D + k0 + kc);
        }
        CP_COMMIT();
    };

    const int NT = IN_D / BK;   // 32
    loadA(0); stsA(0);
    loadA(1);
    cpB(0); cpB(1);
    for (int i = 0; i < NT; i++) {
        const int p = i % SST;
        if (i + 1 < NT) { CP_WAIT(1); } else { CP_WAIT(0); }
        __syncthreads();
        if (i + 1 < NT) stsA((i + 1) % SST);
        if (i + 2 < NT) { loadA(i + 2); cpB(i + 2); }
        const uint32_t aP = aBase + (uint32_t)(p * ASTRIDE) * 4;
        const uint32_t bP = bBase + (uint32_t)(p * BSTRIDE) * 4;
#pragma unroll
        for (int ks = 0; ks < 4; ks++) {
            const int k0 = ks * 8;
            uint32_t af[4][4], bf[4][2];
#pragma unroll
            for (int mt = 0; mt < 4; mt++)
                ldm_x4(af[mt][0], af[mt][1], af[mt][2], af[mt][3],
                       aP + (uint32_t)(mt * 16 * BKP + k0) * 4);
#pragma unroll
            for (int h = 0; h < 2; h++)
                ldm_x4(bf[2*h][0], bf[2*h][1], bf[2*h+1][0], bf[2*h+1][1],
                       bP + (uint32_t)(h * 16 * BKP + k0) * 4);
#pragma unroll
            for (int mt = 0; mt < 4; mt++)
#pragma unroll
                for (int nt = 0; nt < 4; nt++)
                    mma_tf32(acc[mt][nt][0], acc[mt][nt][1], acc[mt][nt][2], acc[mt][nt][3],
                             af[mt][0], af[mt][1], af[mt][2], af[mt][3],
                             bf[nt][0], bf[nt][1]);
        }
    }
    __syncthreads();

    if (bx == 2) {
#pragma unroll
        for (int mt = 0; mt < 4; mt++) {
            int row = row0 + wm + mt * 16 + ly;
#pragma unroll
            for (int nt = 0; nt < 4; nt++) {
                int col = wn + nt * 8 + 2 * lx;
                float2 v0 = {acc[mt][nt][0], acc[mt][nt][1]};
                float2 v1 = {acc[mt][nt][2], acc[mt][nt][3]};
                *(float2*)(g_C + (size_t)row * ER_N + col) = v0;
                *(float2*)(g_C + (size_t)(row + 8) * ER_N + col) = v1;
            }
        }
        return;
    }

    // gate-logit epilogue (bx = 0,1)
    float* eWg2  = smem;
    float* ePart = smem + 1024;
    {
        int c = tid >> 1, half = tid & 1;
        *(float4*)&eWg2[c * 8 + half * 4] =
            *(const float4*)&Wg2[(size_t)(bx * 128 + c) * E_N + half * 4];
    }
    __syncthreads();

    const int nw = wid >> 1;
    float bgv[4][2];
#pragma unroll
    for (int nt = 0; nt < 4; nt++) {
        int colh = bx * 128 + wn + nt * 8 + 2 * lx;
        bgv[nt][0] = bg1[colh]; bgv[nt][1] = bg1[colh + 1];
    }

#pragma unroll
    for (int mt = 0; mt < 4; mt++) {
        float la0[8], la1[8];
#pragma unroll
        for (int e = 0; e < 8; e++) { la0[e] = 0.f; la1[e] = 0.f; }
#pragma unroll
        for (int nt = 0; nt < 4; nt++) {
            int c0 = wn + nt * 8 + 2 * lx;
            float h00 = fmaxf(acc[mt][nt][0] + bgv[nt][0], 0.f);
            float h01 = fmaxf(acc[mt][nt][1] + bgv[nt][1], 0.f);
            float h10 = fmaxf(acc[mt][nt][2] + bgv[nt][0], 0.f);
            float h11 = fmaxf(acc[mt][nt][3] + bgv[nt][1], 0.f);
            const float* w0 = &eWg2[c0 * 8];
            const float* w1 = &eWg2[(c0 + 1) * 8];
#pragma unroll
            for (int e = 0; e < 8; e++) {
                la0[e] = fmaf(h00, w0[e], fmaf(h01, w1[e], la0[e]));
                la1[e] = fmaf(h10, w0[e], fmaf(h11, w1[e], la1[e]));
            }
        }
#pragma unroll
        for (int e = 0; e < 8; e++) {
            la0[e] += __shfl_xor_sync(0xffffffffu, la0[e], 1);
            la0[e] += __shfl_xor_sync(0xffffffffu, la0[e], 2);
            la1[e] += __shfl_xor_sync(0xffffffffu, la1[e], 1);
            la1[e] += __shfl_xor_sync(0xffffffffu, la1[e], 2);
        }
        if (lx == 0) {
            int r0 = wm + mt * 16 + ly;
            float* p0 = &ePart[(nw * 128 + r0) * 8];
            float* p1 = &ePart[(nw * 128 + r0 + 8) * 8];
#pragma unroll
            for (int e = 0; e < 8; e += 4) {
                *(float4*)&p0[e] = make_float4(la0[e], la0[e+1], la0[e+2], la0[e+3]);
                *(float4*)&p1[e] = make_float4(la1[e], la1[e+1], la1[e+2], la1[e+3]);
            }
        }
    }
    __syncthreads();
#pragma unroll
    for (int k = 0; k < 4; k++) {
        int idx = tid * 4 + k;
        int row = idx >> 3, e = idx & 7;
        float s = ePart[(0 * 128 + row) * 8 + e];
        s += ePart[(1 * 128 + row) * 8 + e];
        s += ePart[(2 * 128 + row) * 8 + e];
        s += ePart[(3 * 128 + row) * 8 + e];
        atomicAdd(&g_logits[(size_t)(row0 + row) * E_N + e], s);
    }
}

// ---------------------------------------------------------------- K2: gate (slim)
__global__ void __launch_bounds__(256) k_gate(
    const float* __restrict__ bg2, const float* __restrict__ S)
{
    const int warp = threadIdx.x >> 5;
    const int lane = threadIdx.x & 31;
    const int n = blockIdx.x * 8 + warp;
    if (n >= N_TOK) return;

    float4 l0 = *(const float4*)&g_logits[(size_t)n * E_N];
    float4 l1 = *(const float4*)&g_logits[(size_t)n * E_N + 4];
    float4 b0 = *(const float4*)&bg2[0];
    float4 b1 = *(const float4*)&bg2[4];
    float acc[E_N] = {l0.x + b0.x, l0.y + b0.y, l0.z + b0.z, l0.w + b0.w,
                      l1.x + b1.x, l1.y + b1.y, l1.z + b1.z, l1.w + b1.w};

    int i0 = 0; float v0 = acc[0];
#pragma unroll
    for (int e = 1; e < E_N; e++) if (acc[e] > v0) { v0 = acc[e]; i0 = e; }
    int i1 = -1; float v1 = -3.0e38f;
#pragma unroll
    for (int e = 0; e < E_N; e++) if (e != i0 && acc[e] > v1) { v1 = acc[e]; i1 = e; }

    float e1 = expf(v1 - v0);
    float s  = 1.f + e1;
    float g0 = 1.f / s;
    float g1 = e1 / s;

    float* c = g_C + (size_t)n * ER_N;
#pragma unroll
    for (int q = 0; q < 4; q++) {
        int j = lane + q * 32;
        float t = c[j];
        int e = j >> 4, r = j & 15;
        float g = (e == i0) ? g0 : ((e == i1) ? g1 : 0.f);
        c[j] = tf32rf(g * S[e * R_N + r] * t);
    }
}

// ---------------------------------------------------------------- K3: main
__global__ void __launch_bounds__(NTHR, 2) k_main_mma(
    const float* __restrict__ X, const float* __restrict__ bias,
    float* __restrict__ out)
{
    extern __shared__ float smem[];
    const uint32_t sb = smem_u32(smem);
    const int tid = threadIdx.x, wid = tid >> 5, lane = tid & 31;
    const int ly = lane >> 2, lx = lane & 3;
    const int row0 = blockIdx.y * BM;
    const int col0 = blockIdx.x * BN;
    const int wm = (wid & 1) * 64;
    const int wn = (wid >> 1) * 32;

    const int rowA = ((lane >> 3) & 1) * 8 + (lane & 7);
    const int colA = (lane >> 4) * 4;
    const int rowB = ((lane >> 4) & 1) * 8 + (lane & 7);
    const int colB = ((lane >> 3) & 1) * 4;
    const uint32_t aBase = sb + (uint32_t)A_OFF(0, wm + rowA, colA) * 4;
    const uint32_t bBase = sb + (uint32_t)B_OFF(0, wn + rowB, colB) * 4;

    float acc[4][4][4];
#pragma unroll
    for (int mt = 0; mt < 4; mt++)
#pragma unroll
        for (int nt = 0; nt < 4; nt++)
#pragma unroll
            for (int r = 0; r < 4; r++) acc[mt][nt][r] = 0.f;

    float4 araw[4];
    auto loadA = [&](int kt) {
        const int k0 = kt * BK;
        if (k0 < IN_D) {
#pragma unroll
            for (int q = 0; q < 4; q++) {
                int u = tid + q * NTHR, m = u >> 3, kc = (u & 7) << 2;
                araw[q] = *(const float4*)(X + (size_t)(row0 + m) * IN_D + k0 + kc);
            }
        } else {
            const int kk = k0 - IN_D;
#pragma unroll
            for (int q = 0; q < 4; q++) {
                int u = tid + q * NTHR, m = u >> 3, kc = (u & 7) << 2;
                araw[q] = *(const float4*)(g_C + (size_t)(row0 + m) * ER_N + kk + kc);
            }
        }
    };
    auto stsA = [&](int p) {
#pragma unroll
        for (int q = 0; q < 4; q++) {
            int u = tid + q * NTHR, m = u >> 3, kc = (u & 7) << 2;
            float4 v;
            v.x = tf32rf(araw[q].x); v.y = tf32rf(araw[q].y);
            v.z = tf32rf(araw[q].z); v.w = tf32rf(araw[q].w);
            *(float4*)&smem[A_OFF(p, m, kc)] = v;
        }
    };
    auto cpB = [&](int kt) {
        const int p = kt % SST, k0 = kt * BK;
        if (k0 < IN_D) {
#pragma unroll
            for (int q = 0; q < 4; q++) {
                int u = tid + q * NTHR, n = u >> 3, kc = (u & 7) << 2;
                cp16(sb + B_OFF(p, n, kc) * 4, g_Wmr + (size_t)(col0 + n) * IN_D + k0 + kc);
            }
        } else {
            const int kk = k0 - IN_D;
#pragma unroll
            for (int q = 0; q < 4; q++) {
                int u = tid + q * NTHR, n = u >> 3, kc = (u & 7) << 2;
                int kg = kk + kc, e = kg >> 4, r0 = kg & 15;
                cp16(sb + B_OFF(p, n, kc) * 4,
                     g_Ur + ((size_t)e * OUT_D + (col0 + n)) * R_N + r0);
            }
        }
        CP_COMMIT();
    };

    const int NT = (IN_D + ER_N) / BK;   // 36
    loadA(0); stsA(0);
    loadA(1);
    cpB(0); cpB(1);
    for (int i = 0; i < NT; i++) {
        const int p = i % SST;
        if (i + 1 < NT) { CP_WAIT(1); } else { CP_WAIT(0); }
        __syncthreads();
        if (i + 1 < NT) stsA((i + 1) % SST);
        if (i + 2 < NT) { loadA(i + 2); cpB(i + 2); }
        const uint32_t aP = aBase + (uint32_t)(p * ASTRIDE) * 4;
        const uint32_t bP = bBase + (uint32_t)(p * BSTRIDE) * 4;
#pragma unroll
        for (int ks = 0; ks < 4; ks++) {
            const int k0 = ks * 8;
            uint32_t af[4][4], bf[4][2];
#pragma unroll
            for (int mt = 0; mt < 4; mt++)
                ldm_x4(af[mt][0], af[mt][1], af[mt][2], af[mt][3],
                       aP + (uint32_t)(mt * 16 * BKP + k0) * 4);
#pragma unroll
            for (int h = 0; h < 2; h++)
                ldm_x4(bf[2*h][0], bf[2*h][1], bf[2*h+1][0], bf[2*h+1][1],
                       bP + (uint32_t)(h * 16 * BKP + k0) * 4);
#pragma unroll
            for (int mt = 0; mt < 4; mt++)
#pragma unroll
                for (int nt = 0; nt < 4; nt++)
                    mma_tf32(acc[mt][nt][0], acc[mt][nt][1], acc[mt][nt][2], acc[mt][nt][3],
                             af[mt][0], af[mt][1], af[mt][2], af[mt][3],
                             bf[nt][0], bf[nt][1]);
        }
    }

#pragma unroll
    for (int mt = 0; mt < 4; mt++) {
        int row = row0 + wm + mt * 16 + ly;
#pragma unroll
        for (int nt = 0; nt < 4; nt++) {
            int col = col0 + wn + nt * 8 + 2 * lx;
            float b0 = bias[col], b1 = bias[col + 1];
            float2 v0 = {acc[mt][nt][0] + b0, acc[mt][nt][1] + b1};
            float2 v1 = {acc[mt][nt][2] + b0, acc[mt][nt][3] + b1};
            *(float2*)(out + (size_t)row * OUT_D + col) = v0;
            *(float2*)(out + (size_t)(row + 8) * OUT_D + col) = v1;
        }
    }
}

// ---------------------------------------------------------------- launch
extern "C" void kernel_launch(void* const* d_in, const int* in_sizes, int n_in,
                              void* d_out, int out_size)
{
    const float* x    = (const float*)d_in[0];
    const float* wm   = (const float*)d_in[1];
    const float* bias = (const float*)d_in[2];
    const float* U    = (const float*)d_in[3];
    const float* S    = (const float*)d_in[4];
    const float* V    = (const float*)d_in[5];
    const float* Wg1  = (const float*)d_in[6];
    const float* bg1  = (const float*)d_in[7];
    const float* Wg2  = (const float*)d_in[8];
    const float* bg2  = (const float*)d_in[9];
    float* out = (float*)d_out;

    cudaFuncSetAttribute(k_proj_mma, cudaFuncAttributeMaxDynamicSharedMemorySize, SMEM_BYTES);
    cudaFuncSetAttribute(k_main_mma, cudaFuncAttributeMaxDynamicSharedMemorySize, SMEM_BYTES);

    k_prep<<<NB_R + NB_TR, 256>>>(wm, U, V, Wg1);

    k_proj_mma<<<dim3(3, N_TOK / BM), NTHR, SMEM_BYTES>>>(x, bg1, Wg2);

    k_gate<<<N_TOK / 8, 256>>>(bg2, S);

    k_main_mma<<<dim3(OUT_D / BN, N_TOK / BM), NTHR, SMEM_BYTES>>>(x, bias, out);
}